// round 13
// baseline (speedup 1.0000x reference)
#include <cuda_runtime.h>
#include <cuda_fp16.h>
#include <math.h>
#include <stdint.h>

#define Bb 4
#define Nn 2048
#define Dd 2048
typedef __half f16;

// ---- scratch (static __device__; no allocations allowed) ----
__device__ f16 g_cn_hi[(size_t)Bb * Nn * Dd];
__device__ f16 g_dat_hi[(size_t)Bb * Nn * Dd];
__device__ f16 g_sim_hi[(size_t)Bb * Nn * Nn];
__device__ f16 g_pe_hi[(size_t)Nn * Dd];
__device__ f16 g_v_hi[(size_t)Bb * Nn * Nn];
__device__ f16 g_ctr_hi[(size_t)Bb * Nn * Dd];
__device__ f16 g_weT_hi[(size_t)Dd * Dd];
__device__ f16 g_wmT_hi[(size_t)2 * Dd * Dd];
__device__ float g_csum[Bb * Nn];

// =================== helpers ===================

__device__ __forceinline__ void cp16(uint32_t s, const void* g) {
    asm volatile("cp.async.cg.shared.global [%0], [%1], 16;" :: "r"(s), "l"(g));
}
__device__ __forceinline__ void cp_commit() {
    asm volatile("cp.async.commit_group;" ::: "memory");
}
__device__ __forceinline__ void cp_wait2() {
    asm volatile("cp.async.wait_group 2;" ::: "memory");
}

__device__ __forceinline__ void ldsm4(uint32_t& r0, uint32_t& r1, uint32_t& r2,
                                      uint32_t& r3, uint32_t a) {
    asm volatile("ldmatrix.sync.aligned.m8n8.x4.shared.b16 {%0,%1,%2,%3}, [%4];"
                 : "=r"(r0), "=r"(r1), "=r"(r2), "=r"(r3) : "r"(a));
}

__device__ __forceinline__ void mma_f16(float* c, const uint32_t* a, const uint32_t* b) {
    asm volatile("mma.sync.aligned.m16n8k16.row.col.f32.f16.f16.f32 "
                 "{%0,%1,%2,%3}, {%4,%5,%6,%7}, {%8,%9}, {%0,%1,%2,%3};"
                 : "+f"(c[0]), "+f"(c[1]), "+f"(c[2]), "+f"(c[3])
                 : "r"(a[0]), "r"(a[1]), "r"(a[2]), "r"(a[3]), "r"(b[0]), "r"(b[1]));
}

// =================== MMA GEMM core ===================
// CTA tile 128(m) x 128(n), K-chunk 32. 8 warps: 4(m) x 2(n) -> warp 32m x 64n.
// 1-pass: 2 tiles/stage (A, B; 8KB each). 6-stage ring (96KB) -> 2 CTAs/SM.
// ONE __syncthreads + ONE wait per 2 chunks (paired-sync pipeline).

#define TILE_B   8192
#define NSTAGE   6

// swizzled smem offset within a 128x32-f16 tile (row stride 64B, 4x 16B cols)
__device__ __forceinline__ uint32_t swz(uint32_t row, uint32_t c16) {
    return row * 64u + ((c16 ^ ((row >> 1) & 3u)) << 4);
}

// srcf(kc, P[2], ld[2]): K-major pointers for A, B at this K-chunk. KC even, >= 4.
template <typename SrcF>
__device__ __forceinline__ void mma_gemm(int KC, SrcF srcf, float c[2][8][4]) {
    constexpr int STAGE_B = 2 * TILE_B;
    extern __shared__ char smem[];
    const int tid = threadIdx.x;
    const int lane = tid & 31;
    const int wid = tid >> 5;
    const int wm = wid >> 1, wn = wid & 1;
    const uint32_t sbase = (uint32_t)__cvta_generic_to_shared(smem);

    auto load_stage = [&](int kc, int s) {
        const f16* P[2]; int ld[2];
        srcf(kc, P, ld);
        const int row = tid >> 1;
        const int c0 = (tid & 1) * 2;
        #pragma unroll
        for (int t = 0; t < 2; ++t) {
            const f16* src = P[t] + (size_t)row * ld[t] + c0 * 8;
            uint32_t dst = sbase + s * STAGE_B + t * TILE_B;
            cp16(dst + swz(row, c0),     src);
            cp16(dst + swz(row, c0 + 1), src + 8);
        }
    };

    auto compute = [&](int s) {
        const uint32_t base = sbase + s * STAGE_B;
        #pragma unroll
        for (int ks = 0; ks < 2; ++ks) {
            uint32_t a[2][4], bh[8][2];
            #pragma unroll
            for (int mi = 0; mi < 2; ++mi) {
                uint32_t row = wm * 32 + mi * 16 + (lane & 15);
                uint32_t c16 = ks * 2 + (lane >> 4);
                uint32_t off = swz(row, c16);
                ldsm4(a[mi][0], a[mi][1], a[mi][2], a[mi][3], base + off);
            }
            #pragma unroll
            for (int j2 = 0; j2 < 4; ++j2) {
                uint32_t row = wn * 64 + j2 * 16 + ((lane >> 4) << 3) + (lane & 7);
                uint32_t c16 = ks * 2 + ((lane >> 3) & 1);
                uint32_t off = swz(row, c16);
                ldsm4(bh[2 * j2][0], bh[2 * j2][1], bh[2 * j2 + 1][0], bh[2 * j2 + 1][1],
                      base + TILE_B + off);
            }
            #pragma unroll
            for (int mi = 0; mi < 2; ++mi)
                #pragma unroll
                for (int nj = 0; nj < 8; ++nj)
                    mma_f16(c[mi][nj], a[mi], bh[nj]);
        }
    };

    // prefetch 4 chunks into slots 0..3 (one commit-group each)
    #pragma unroll
    for (int p = 0; p < 4; ++p) {
        if (p < KC) load_stage(p, p);
        cp_commit();
    }
    // paired loop: 2 chunks per wait+sync. Empty commit_groups at the tail
    // keep the wait_group bookkeeping exact.
    int s = 0, sl = 4;
    for (int kc = 0; kc < KC; kc += 2) {
        cp_wait2();          // chunks kc, kc+1 arrived (kc+2, kc+3 in flight)
        __syncthreads();     // slots sl, sl+1 were computed last pair by all warps
        if (kc + 4 < KC) load_stage(kc + 4, sl);
        cp_commit();
        if (++sl == NSTAGE) sl = 0;
        if (kc + 5 < KC) load_stage(kc + 5, sl);
        cp_commit();
        if (++sl == NSTAGE) sl = 0;
        compute(s);
        if (++s == NSTAGE) s = 0;
        compute(s);
        if (++s == NSTAGE) s = 0;
    }
    __syncthreads();   // smem safe for epilogue reuse
}

// epilogue iteration: calls body(row, col, v0, v1) for each accumulator pair
template <typename BodyF>
__device__ __forceinline__ void epi_loop(int m0, int n0, float c[2][8][4], BodyF body) {
    const int lane = threadIdx.x & 31;
    const int wid = threadIdx.x >> 5;
    const int wm = wid >> 1, wn = wid & 1;
    #pragma unroll
    for (int mi = 0; mi < 2; ++mi)
        #pragma unroll
        for (int nj = 0; nj < 8; ++nj)
            #pragma unroll
            for (int h = 0; h < 2; ++h) {
                const int row = m0 + wm * 32 + mi * 16 + (lane >> 2) + h * 8;
                const int col = n0 + wn * 64 + nj * 8 + (lane & 3) * 2;
                body(row, col, c[mi][nj][2 * h], c[mi][nj][2 * h + 1]);
            }
}

// =================== GEMM kernels ===================

// sim = relu(cn @ cn^T), 1-pass, symmetric: upper-tri tiles only, mirrored
// through padded smem; row sums fused (atomicAdd into g_csum).
// grid.x = 136 (= 16*17/2)
#define EPAD 136
#define SMEM_GE (NSTAGE * 2 * TILE_B)   // 98304
__global__ __launch_bounds__(256, 2) void k_mma_sim() {
    const int b = blockIdx.z;
    int t = blockIdx.x, ti = 0;
    while (t >= 16 - ti) { t -= 16 - ti; ++ti; }
    const int tj = ti + t;
    const int m0 = ti * 128, n0 = tj * 128;

    float c[2][8][4] = {};
    mma_gemm(Dd / 32,
        [&](int kc, const f16** P, int* ld) {
            size_t a = ((size_t)b * Nn + m0) * Dd + kc * 32;
            size_t o = ((size_t)b * Nn + n0) * Dd + kc * 32;
            P[0] = g_cn_hi + a; P[1] = g_cn_hi + o;
            ld[0] = ld[1] = Dd;
        }, c);

    extern __shared__ char smem[];
    f16* sh = (f16*)smem;   // [128][EPAD]
    epi_loop(0, 0, c, [&](int r, int col, float v0, float v1) {
        sh[r * EPAD + col]     = __float2half_rn(fmaxf(v0, 0.f));
        sh[r * EPAD + col + 1] = __float2half_rn(fmaxf(v1, 0.f));
    });
    __syncthreads();

    // write normal orientation
    for (int idx = threadIdx.x; idx < 128 * 16; idx += 256) {
        const int r = idx >> 4, seg = idx & 15;
        size_t o = ((size_t)b * Nn + m0 + r) * Nn + n0 + seg * 8;
        *(uint4*)(g_sim_hi + o) = *(const uint4*)(sh + r * EPAD + seg * 8);
    }
    // mirrored orientation (skip on diagonal tiles)
    if (ti != tj) {
        for (int idx = threadIdx.x; idx < 128 * 16; idx += 256) {
            const int cc = idx >> 4, rseg = idx & 15;
            f16 th[8];
            #pragma unroll
            for (int q = 0; q < 8; ++q)
                th[q] = sh[(rseg * 8 + q) * EPAD + cc];
            size_t o = ((size_t)b * Nn + n0 + cc) * Nn + m0 + rseg * 8;
            *(uint4*)(g_sim_hi + o) = *(const uint4*)th;
        }
    }
    // fused row sums: tid 0-127 -> row-sums into csum[m0+r];
    // tid 128-255 -> mirrored column-sums into csum[n0+c] (off-diagonal only).
    {
        const int tid = threadIdx.x;
        if (tid < 128) {
            float s = 0.f;
            const __half2* rp = (const __half2*)(sh + tid * EPAD);
            #pragma unroll 16
            for (int q = 0; q < 64; ++q) {
                float2 f = __half22float2(rp[q]);
                s += f.x + f.y;
            }
            atomicAdd(&g_csum[b * Nn + m0 + tid], s);
        } else if (ti != tj) {
            const int cc = tid - 128;
            float s2 = 0.f;
            for (int rr = 0; rr < 128; ++rr)
                s2 += __half2float(sh[rr * EPAD + cc]);
            atomicAdd(&g_csum[b * Nn + n0 + cc], s2);
        }
    }
}

// v = posenc @ sim, 1-pass (sim symmetric: B[n][k] = sim[n][k])
__global__ __launch_bounds__(256, 2) void k_mma_v() {
    const int b = blockIdx.z, m0 = blockIdx.y * 128, n0 = blockIdx.x * 128;
    float c[2][8][4] = {};
    mma_gemm(Nn / 32,
        [&](int kc, const f16** P, int* ld) {
            size_t a = (size_t)m0 * Dd + kc * 32;
            size_t o = ((size_t)b * Nn + n0) * Nn + kc * 32;
            P[0] = g_pe_hi + a; P[1] = g_sim_hi + o;
            ld[0] = Dd; ld[1] = Nn;
        }, c);
    epi_loop(m0, n0, c, [&](int row, int col, float v0, float v1) {
        size_t o = ((size_t)b * Nn + row) * Nn + col;
        *(__half2*)(g_v_hi + o) = __half2(__float2half_rn(v0), __float2half_rn(v1));
    });
}

// counter = softplus(v @ W_exp[1:] + csum*W_exp[0] + b_exp), 1-pass
__global__ __launch_bounds__(256, 2) void k_mma_counter(const float* __restrict__ W_exp,
                                                        const float* __restrict__ b_exp) {
    const int b = blockIdx.z, m0 = blockIdx.y * 128, n0 = blockIdx.x * 128;
    float c[2][8][4] = {};
    mma_gemm(Nn / 32,
        [&](int kc, const f16** P, int* ld) {
            size_t a = ((size_t)b * Nn + m0) * Nn + kc * 32;
            size_t o = (size_t)n0 * Dd + kc * 32;
            P[0] = g_v_hi + a; P[1] = g_weT_hi + o;
            ld[0] = Nn; ld[1] = Dd;
        }, c);
    epi_loop(m0, n0, c, [&](int row, int col, float v0, float v1) {
        const float cs = g_csum[b * Nn + row];
        float x0 = v0 + cs * W_exp[col] + b_exp[col];
        float x1 = v1 + cs * W_exp[col + 1] + b_exp[col + 1];
        float s0 = fmaxf(x0, 0.f) + log1pf(expf(-fabsf(x0)));
        float s1 = fmaxf(x1, 0.f) + log1pf(expf(-fabsf(x1)));
        size_t o = ((size_t)b * Nn + row) * Dd + col;
        *(__half2*)(g_ctr_hi + o) = __half2(__float2half_rn(s0), __float2half_rn(s1));
    });
}

// out = data @ W_merge[:D] + counter @ W_merge[D:], 1-pass, fp32 out
__global__ __launch_bounds__(256, 2) void k_mma_out(float* __restrict__ outp) {
    const int b = blockIdx.z, m0 = blockIdx.y * 128, n0 = blockIdx.x * 128;
    float c[2][8][4] = {};
    mma_gemm(2 * Dd / 32,
        [&](int kc, const f16** P, int* ld) {
            if (kc < Dd / 32) {
                size_t a = ((size_t)b * Nn + m0) * Dd + kc * 32;
                size_t o = (size_t)n0 * (2 * Dd) + kc * 32;
                P[0] = g_dat_hi + a; P[1] = g_wmT_hi + o;
            } else {
                size_t a = ((size_t)b * Nn + m0) * Dd + (kc - Dd / 32) * 32;
                size_t o = (size_t)n0 * (2 * Dd) + Dd + (kc - Dd / 32) * 32;
                P[0] = g_ctr_hi + a; P[1] = g_wmT_hi + o;
            }
            ld[0] = Dd; ld[1] = 2 * Dd;
        }, c);
    epi_loop(m0, n0, c, [&](int row, int col, float v0, float v1) {
        size_t o = ((size_t)b * Nn + row) * Dd + col;
        float2 v; v.x = v0; v.y = v1;
        *(float2*)(outp + o) = v;
    });
}

// =================== prep / pointwise kernels ===================

__global__ __launch_bounds__(256) void k_prep_data(const float* __restrict__ data) {
    const int row = blockIdx.x;  // b*Nn + n
    if (threadIdx.x == 0) g_csum[row] = 0.f;   // zero for fused rowsum atomics
    const float* in = data + (size_t)row * Dd;
    float s = 0.f;
    for (int i = threadIdx.x; i < Dd; i += 256) { float v = in[i]; s += v * v; }
    __shared__ float red[32];
    #pragma unroll
    for (int o = 16; o; o >>= 1) s += __shfl_down_sync(0xffffffffu, s, o);
    if ((threadIdx.x & 31) == 0) red[threadIdx.x >> 5] = s;
    __syncthreads();
    if (threadIdx.x < 32) {
        float v = (threadIdx.x < 8) ? red[threadIdx.x] : 0.f;
        #pragma unroll
        for (int o = 4; o; o >>= 1) v += __shfl_down_sync(0xffffffffu, v, o);
        if (threadIdx.x == 0) red[0] = rsqrtf(fmaxf(v, 1e-12f));
    }
    __syncthreads();
    const float r = red[0];
    size_t base = (size_t)row * Dd;
    for (int i = threadIdx.x; i < Dd; i += 256) {
        float v = in[i];
        g_dat_hi[base + i] = __float2half_rn(v);
        g_cn_hi[base + i] = __float2half_rn(v * r);
    }
}

__global__ __launch_bounds__(256) void k_prep_pe() {
    const int idx = blockIdx.x * 256 + threadIdx.x;
    const int n = idx / Dd;
    const int i = idx - n * Dd;
    const float e = (float)(2 * (i / 2)) / (float)Dd;
    const float rate = exp2f(-13.28771238f * e);
    const float ang = (float)n * rate;
    float v = (i & 1) ? cosf(ang) : sinf(ang);
    g_pe_hi[idx] = __float2half_rn(v);
}

// W_expT[n][k] = W_exp[(k+1)*Dd + n]. Tile 64k x 32n; half2 writes (128B/warp).
__global__ void k_prep_weT(const float* __restrict__ W_exp) {
    __shared__ float t[32][65];   // [n][k]
    const int n0 = blockIdx.x * 32;
    const int k0 = blockIdx.y * 64;
    #pragma unroll
    for (int i = 0; i < 2; ++i) {
        int k = 2 * threadIdx.y + i;
        t[threadIdx.x][k] = W_exp[(size_t)(k0 + k + 1) * Dd + n0 + threadIdx.x];
    }
    __syncthreads();
    const int n = threadIdx.y;
    const int kk = 2 * threadIdx.x;
    __half2 h = __floats2half2_rn(t[n][kk], t[n][kk + 1]);
    *(__half2*)(g_weT_hi + (size_t)(n0 + n) * Dd + k0 + kk) = h;
}

// W_mergeT[n][k] = W_merge[k*Dd + n], k in [0,4096). Tile 64k x 32n.
__global__ void k_prep_wmT(const float* __restrict__ W_merge) {
    __shared__ float t[32][65];   // [n][k]
    const int n0 = blockIdx.x * 32;
    const int k0 = blockIdx.y * 64;
    #pragma unroll
    for (int i = 0; i < 2; ++i) {
        int k = 2 * threadIdx.y + i;
        t[threadIdx.x][k] = W_merge[(size_t)(k0 + k) * Dd + n0 + threadIdx.x];
    }
    __syncthreads();
    const int n = threadIdx.y;
    const int kk = 2 * threadIdx.x;
    __half2 h = __floats2half2_rn(t[n][kk], t[n][kk + 1]);
    *(__half2*)(g_wmT_hi + (size_t)(n0 + n) * (2 * Dd) + k0 + kk) = h;
}

// =================== launch ===================

extern "C" void kernel_launch(void* const* d_in, const int* in_sizes, int n_in,
                              void* d_out, int out_size) {
    const float* data    = (const float*)d_in[0];
    const float* W_exp   = (const float*)d_in[1];
    const float* b_exp   = (const float*)d_in[2];
    const float* W_merge = (const float*)d_in[3];
    float* out = (float*)d_out;
    (void)in_sizes; (void)n_in; (void)out_size;

    cudaFuncSetAttribute(k_mma_sim,     cudaFuncAttributeMaxDynamicSharedMemorySize, SMEM_GE);
    cudaFuncSetAttribute(k_mma_v,       cudaFuncAttributeMaxDynamicSharedMemorySize, SMEM_GE);
    cudaFuncSetAttribute(k_mma_counter, cudaFuncAttributeMaxDynamicSharedMemorySize, SMEM_GE);
    cudaFuncSetAttribute(k_mma_out,     cudaFuncAttributeMaxDynamicSharedMemorySize, SMEM_GE);

    const dim3 tgrid(Nn / 128, Nn / 128, Bb);

    k_prep_data<<<Bb * Nn, 256>>>(data);
    k_prep_pe<<<(Nn * Dd) / 256, 256>>>();
    k_prep_weT<<<dim3(Dd / 32, Dd / 64), dim3(32, 32)>>>(W_exp);
    k_prep_wmT<<<dim3(Dd / 32, (2 * Dd) / 64), dim3(32, 32)>>>(W_merge);

    k_mma_sim<<<dim3(136, 1, Bb), 256, SMEM_GE>>>();
    k_mma_v<<<tgrid, 256, SMEM_GE>>>();
    k_mma_counter<<<tgrid, 256, SMEM_GE>>>(W_exp, b_exp);
    k_mma_out<<<tgrid, 256, SMEM_GE>>>(out);
}

// round 14
// speedup vs baseline: 1.0346x; 1.0346x over previous
#include <cuda_runtime.h>
#include <cuda_fp16.h>
#include <math.h>
#include <stdint.h>

#define Bb 4
#define Nn 2048
#define Dd 2048
typedef __half f16;

// ---- scratch (static __device__; no allocations allowed) ----
__device__ f16 g_cn_hi[(size_t)Bb * Nn * Dd];
__device__ f16 g_dat_hi[(size_t)Bb * Nn * Dd];
__device__ f16 g_sim_hi[(size_t)Bb * Nn * Nn];
__device__ f16 g_pe_hi[(size_t)Nn * Dd];
__device__ f16 g_v_hi[(size_t)Bb * Nn * Nn];
__device__ f16 g_ctr_hi[(size_t)Bb * Nn * Dd];
__device__ f16 g_weT_hi[(size_t)Dd * Dd];
__device__ f16 g_wmT_hi[(size_t)2 * Dd * Dd];
__device__ float g_csum[Bb * Nn];

// =================== helpers ===================

__device__ __forceinline__ void cp16(uint32_t s, const void* g) {
    asm volatile("cp.async.cg.shared.global [%0], [%1], 16;" :: "r"(s), "l"(g));
}
__device__ __forceinline__ void cp_commit() {
    asm volatile("cp.async.commit_group;" ::: "memory");
}
__device__ __forceinline__ void cp_wait2() {
    asm volatile("cp.async.wait_group 2;" ::: "memory");
}

__device__ __forceinline__ void ldsm4(uint32_t& r0, uint32_t& r1, uint32_t& r2,
                                      uint32_t& r3, uint32_t a) {
    asm volatile("ldmatrix.sync.aligned.m8n8.x4.shared.b16 {%0,%1,%2,%3}, [%4];"
                 : "=r"(r0), "=r"(r1), "=r"(r2), "=r"(r3) : "r"(a));
}

__device__ __forceinline__ void mma_f16(float* c, const uint32_t* a, const uint32_t* b) {
    asm volatile("mma.sync.aligned.m16n8k16.row.col.f32.f16.f16.f32 "
                 "{%0,%1,%2,%3}, {%4,%5,%6,%7}, {%8,%9}, {%0,%1,%2,%3};"
                 : "+f"(c[0]), "+f"(c[1]), "+f"(c[2]), "+f"(c[3])
                 : "r"(a[0]), "r"(a[1]), "r"(a[2]), "r"(a[3]), "r"(b[0]), "r"(b[1]));
}

// =================== MMA GEMM core (R12-proven config) ===================
// CTA tile 128(m) x 128(n), K-chunk 32. 8 warps: 4(m) x 2(n) -> warp 32m x 64n.
// 1-pass: 2 tiles/stage (A, B; 8KB each), 4 stages = 64KB -> 2 CTAs/SM.

#define TILE_B   8192
#define NSTAGE   4

// swizzled smem offset within a 128x32-f16 tile (row stride 64B, 4x 16B cols)
__device__ __forceinline__ uint32_t swz(uint32_t row, uint32_t c16) {
    return row * 64u + ((c16 ^ ((row >> 1) & 3u)) << 4);
}

// srcf(kc, P[2], ld[2]): K-major pointers for A, B at this K-chunk
template <typename SrcF>
__device__ __forceinline__ void mma_gemm(int KC, SrcF srcf, float c[2][8][4]) {
    constexpr int STAGE_B = 2 * TILE_B;
    extern __shared__ char smem[];
    const int tid = threadIdx.x;
    const int lane = tid & 31;
    const int wid = tid >> 5;
    const int wm = wid >> 1, wn = wid & 1;
    const uint32_t sbase = (uint32_t)__cvta_generic_to_shared(smem);

    auto load_stage = [&](int kc, int s) {
        const f16* P[2]; int ld[2];
        srcf(kc, P, ld);
        const int row = tid >> 1;
        const int c0 = (tid & 1) * 2;
        #pragma unroll
        for (int t = 0; t < 2; ++t) {
            const f16* src = P[t] + (size_t)row * ld[t] + c0 * 8;
            uint32_t dst = sbase + s * STAGE_B + t * TILE_B;
            cp16(dst + swz(row, c0),     src);
            cp16(dst + swz(row, c0 + 1), src + 8);
        }
    };

    auto compute = [&](int s) {
        const uint32_t base = sbase + s * STAGE_B;
        #pragma unroll
        for (int ks = 0; ks < 2; ++ks) {
            uint32_t a[2][4], bh[8][2];
            #pragma unroll
            for (int mi = 0; mi < 2; ++mi) {
                uint32_t row = wm * 32 + mi * 16 + (lane & 15);
                uint32_t c16 = ks * 2 + (lane >> 4);
                uint32_t off = swz(row, c16);
                ldsm4(a[mi][0], a[mi][1], a[mi][2], a[mi][3], base + off);
            }
            #pragma unroll
            for (int j2 = 0; j2 < 4; ++j2) {
                uint32_t row = wn * 64 + j2 * 16 + ((lane >> 4) << 3) + (lane & 7);
                uint32_t c16 = ks * 2 + ((lane >> 3) & 1);
                uint32_t off = swz(row, c16);
                ldsm4(bh[2 * j2][0], bh[2 * j2][1], bh[2 * j2 + 1][0], bh[2 * j2 + 1][1],
                      base + TILE_B + off);
            }
            #pragma unroll
            for (int mi = 0; mi < 2; ++mi)
                #pragma unroll
                for (int nj = 0; nj < 8; ++nj)
                    mma_f16(c[mi][nj], a[mi], bh[nj]);
        }
    };

    // prefetch 3 stages
    #pragma unroll
    for (int p = 0; p < NSTAGE - 1; ++p) {
        if (p < KC) load_stage(p, p);
        cp_commit();
    }
    for (int kc = 0; kc < KC; ++kc) {
        cp_wait2();
        __syncthreads();
        const int pf = kc + NSTAGE - 1;
        if (pf < KC) load_stage(pf, pf & (NSTAGE - 1));
        cp_commit();
        compute(kc & (NSTAGE - 1));
    }
    __syncthreads();   // smem safe for epilogue reuse
}

// epilogue iteration: calls body(row, col, v0, v1) for each accumulator pair
template <typename BodyF>
__device__ __forceinline__ void epi_loop(int m0, int n0, float c[2][8][4], BodyF body) {
    const int lane = threadIdx.x & 31;
    const int wid = threadIdx.x >> 5;
    const int wm = wid >> 1, wn = wid & 1;
    #pragma unroll
    for (int mi = 0; mi < 2; ++mi)
        #pragma unroll
        for (int nj = 0; nj < 8; ++nj)
            #pragma unroll
            for (int h = 0; h < 2; ++h) {
                const int row = m0 + wm * 32 + mi * 16 + (lane >> 2) + h * 8;
                const int col = n0 + wn * 64 + nj * 8 + (lane & 3) * 2;
                body(row, col, c[mi][nj][2 * h], c[mi][nj][2 * h + 1]);
            }
}

// =================== GEMM kernels ===================

// sim = relu(cn @ cn^T), 1-pass, symmetric: upper-tri tiles only, mirrored
// through padded smem; row sums fused (atomicAdd into g_csum).
// grid.x = 136 (= 16*17/2)
#define EPAD 136
#define SMEM_GE (NSTAGE * 2 * TILE_B)   // 65536
__global__ __launch_bounds__(256, 2) void k_mma_sim() {
    const int b = blockIdx.z;
    int t = blockIdx.x, ti = 0;
    while (t >= 16 - ti) { t -= 16 - ti; ++ti; }
    const int tj = ti + t;
    const int m0 = ti * 128, n0 = tj * 128;

    float c[2][8][4] = {};
    mma_gemm(Dd / 32,
        [&](int kc, const f16** P, int* ld) {
            size_t a = ((size_t)b * Nn + m0) * Dd + kc * 32;
            size_t o = ((size_t)b * Nn + n0) * Dd + kc * 32;
            P[0] = g_cn_hi + a; P[1] = g_cn_hi + o;
            ld[0] = ld[1] = Dd;
        }, c);

    extern __shared__ char smem[];
    f16* sh = (f16*)smem;   // [128][EPAD]
    epi_loop(0, 0, c, [&](int r, int col, float v0, float v1) {
        sh[r * EPAD + col]     = __float2half_rn(fmaxf(v0, 0.f));
        sh[r * EPAD + col + 1] = __float2half_rn(fmaxf(v1, 0.f));
    });
    __syncthreads();

    // write normal orientation
    for (int idx = threadIdx.x; idx < 128 * 16; idx += 256) {
        const int r = idx >> 4, seg = idx & 15;
        size_t o = ((size_t)b * Nn + m0 + r) * Nn + n0 + seg * 8;
        *(uint4*)(g_sim_hi + o) = *(const uint4*)(sh + r * EPAD + seg * 8);
    }
    // mirrored orientation (skip on diagonal tiles)
    if (ti != tj) {
        for (int idx = threadIdx.x; idx < 128 * 16; idx += 256) {
            const int cc = idx >> 4, rseg = idx & 15;
            f16 th[8];
            #pragma unroll
            for (int q = 0; q < 8; ++q)
                th[q] = sh[(rseg * 8 + q) * EPAD + cc];
            size_t o = ((size_t)b * Nn + n0 + cc) * Nn + m0 + rseg * 8;
            *(uint4*)(g_sim_hi + o) = *(const uint4*)th;
        }
    }
    // fused row sums: tid 0-127 -> row-sums into csum[m0+r];
    // tid 128-255 -> mirrored column-sums into csum[n0+c] (off-diagonal only).
    {
        const int tid = threadIdx.x;
        if (tid < 128) {
            float s = 0.f;
            const __half2* rp = (const __half2*)(sh + tid * EPAD);
            #pragma unroll 16
            for (int q = 0; q < 64; ++q) {
                float2 f = __half22float2(rp[q]);
                s += f.x + f.y;
            }
            atomicAdd(&g_csum[b * Nn + m0 + tid], s);
        } else if (ti != tj) {
            const int cc = tid - 128;
            float s2 = 0.f;
            for (int rr = 0; rr < 128; ++rr)
                s2 += __half2float(sh[rr * EPAD + cc]);
            atomicAdd(&g_csum[b * Nn + n0 + cc], s2);
        }
    }
}

// v = posenc @ sim, 1-pass (sim symmetric: B[n][k] = sim[n][k])
__global__ __launch_bounds__(256, 2) void k_mma_v() {
    const int b = blockIdx.z, m0 = blockIdx.y * 128, n0 = blockIdx.x * 128;
    float c[2][8][4] = {};
    mma_gemm(Nn / 32,
        [&](int kc, const f16** P, int* ld) {
            size_t a = (size_t)m0 * Dd + kc * 32;
            size_t o = ((size_t)b * Nn + n0) * Nn + kc * 32;
            P[0] = g_pe_hi + a; P[1] = g_sim_hi + o;
            ld[0] = Dd; ld[1] = Nn;
        }, c);
    epi_loop(m0, n0, c, [&](int row, int col, float v0, float v1) {
        size_t o = ((size_t)b * Nn + row) * Nn + col;
        *(__half2*)(g_v_hi + o) = __half2(__float2half_rn(v0), __float2half_rn(v1));
    });
}

// counter = softplus(v @ W_exp[1:] + csum*W_exp[0] + b_exp), 1-pass
__global__ __launch_bounds__(256, 2) void k_mma_counter(const float* __restrict__ W_exp,
                                                        const float* __restrict__ b_exp) {
    const int b = blockIdx.z, m0 = blockIdx.y * 128, n0 = blockIdx.x * 128;
    float c[2][8][4] = {};
    mma_gemm(Nn / 32,
        [&](int kc, const f16** P, int* ld) {
            size_t a = ((size_t)b * Nn + m0) * Nn + kc * 32;
            size_t o = (size_t)n0 * Dd + kc * 32;
            P[0] = g_v_hi + a; P[1] = g_weT_hi + o;
            ld[0] = Nn; ld[1] = Dd;
        }, c);
    epi_loop(m0, n0, c, [&](int row, int col, float v0, float v1) {
        const float cs = g_csum[b * Nn + row];
        float x0 = v0 + cs * W_exp[col] + b_exp[col];
        float x1 = v1 + cs * W_exp[col + 1] + b_exp[col + 1];
        float s0 = fmaxf(x0, 0.f) + log1pf(expf(-fabsf(x0)));
        float s1 = fmaxf(x1, 0.f) + log1pf(expf(-fabsf(x1)));
        size_t o = ((size_t)b * Nn + row) * Dd + col;
        *(__half2*)(g_ctr_hi + o) = __half2(__float2half_rn(s0), __float2half_rn(s1));
    });
}

// out = data @ W_merge[:D] + counter @ W_merge[D:], 1-pass, fp32 out
__global__ __launch_bounds__(256, 2) void k_mma_out(float* __restrict__ outp) {
    const int b = blockIdx.z, m0 = blockIdx.y * 128, n0 = blockIdx.x * 128;
    float c[2][8][4] = {};
    mma_gemm(2 * Dd / 32,
        [&](int kc, const f16** P, int* ld) {
            if (kc < Dd / 32) {
                size_t a = ((size_t)b * Nn + m0) * Dd + kc * 32;
                size_t o = (size_t)n0 * (2 * Dd) + kc * 32;
                P[0] = g_dat_hi + a; P[1] = g_wmT_hi + o;
            } else {
                size_t a = ((size_t)b * Nn + m0) * Dd + (kc - Dd / 32) * 32;
                size_t o = (size_t)n0 * (2 * Dd) + Dd + (kc - Dd / 32) * 32;
                P[0] = g_ctr_hi + a; P[1] = g_wmT_hi + o;
            }
            ld[0] = Dd; ld[1] = 2 * Dd;
        }, c);
    epi_loop(m0, n0, c, [&](int row, int col, float v0, float v1) {
        size_t o = ((size_t)b * Nn + row) * Dd + col;
        float2 v; v.x = v0; v.y = v1;
        *(float2*)(outp + o) = v;
    });
}

// =================== prep / pointwise kernels ===================

__global__ __launch_bounds__(256) void k_prep_data(const float* __restrict__ data) {
    const int row = blockIdx.x;  // b*Nn + n
    if (threadIdx.x == 0) g_csum[row] = 0.f;   // zero for fused rowsum atomics
    const float* in = data + (size_t)row * Dd;
    float s = 0.f;
    for (int i = threadIdx.x; i < Dd; i += 256) { float v = in[i]; s += v * v; }
    __shared__ float red[32];
    #pragma unroll
    for (int o = 16; o; o >>= 1) s += __shfl_down_sync(0xffffffffu, s, o);
    if ((threadIdx.x & 31) == 0) red[threadIdx.x >> 5] = s;
    __syncthreads();
    if (threadIdx.x < 32) {
        float v = (threadIdx.x < 8) ? red[threadIdx.x] : 0.f;
        #pragma unroll
        for (int o = 4; o; o >>= 1) v += __shfl_down_sync(0xffffffffu, v, o);
        if (threadIdx.x == 0) red[0] = rsqrtf(fmaxf(v, 1e-12f));
    }
    __syncthreads();
    const float r = red[0];
    size_t base = (size_t)row * Dd;
    for (int i = threadIdx.x; i < Dd; i += 256) {
        float v = in[i];
        g_dat_hi[base + i] = __float2half_rn(v);
        g_cn_hi[base + i] = __float2half_rn(v * r);
    }
}

__global__ __launch_bounds__(256) void k_prep_pe() {
    const int idx = blockIdx.x * 256 + threadIdx.x;
    const int n = idx / Dd;
    const int i = idx - n * Dd;
    const float e = (float)(2 * (i / 2)) / (float)Dd;
    const float rate = exp2f(-13.28771238f * e);
    const float ang = (float)n * rate;
    float v = (i & 1) ? cosf(ang) : sinf(ang);
    g_pe_hi[idx] = __float2half_rn(v);
}

// W_expT[n][k] = W_exp[(k+1)*Dd + n]. Tile 64k x 32n; half2 writes (128B/warp).
__global__ void k_prep_weT(const float* __restrict__ W_exp) {
    __shared__ float t[32][65];   // [n][k]
    const int n0 = blockIdx.x * 32;
    const int k0 = blockIdx.y * 64;
    #pragma unroll
    for (int i = 0; i < 2; ++i) {
        int k = 2 * threadIdx.y + i;
        t[threadIdx.x][k] = W_exp[(size_t)(k0 + k + 1) * Dd + n0 + threadIdx.x];
    }
    __syncthreads();
    const int n = threadIdx.y;
    const int kk = 2 * threadIdx.x;
    __half2 h = __floats2half2_rn(t[n][kk], t[n][kk + 1]);
    *(__half2*)(g_weT_hi + (size_t)(n0 + n) * Dd + k0 + kk) = h;
}

// W_mergeT[n][k] = W_merge[k*Dd + n], k in [0,4096). Tile 64k x 32n.
__global__ void k_prep_wmT(const float* __restrict__ W_merge) {
    __shared__ float t[32][65];   // [n][k]
    const int n0 = blockIdx.x * 32;
    const int k0 = blockIdx.y * 64;
    #pragma unroll
    for (int i = 0; i < 2; ++i) {
        int k = 2 * threadIdx.y + i;
        t[threadIdx.x][k] = W_merge[(size_t)(k0 + k) * Dd + n0 + threadIdx.x];
    }
    __syncthreads();
    const int n = threadIdx.y;
    const int kk = 2 * threadIdx.x;
    __half2 h = __floats2half2_rn(t[n][kk], t[n][kk + 1]);
    *(__half2*)(g_wmT_hi + (size_t)(n0 + n) * (2 * Dd) + k0 + kk) = h;
}

// =================== launch ===================

extern "C" void kernel_launch(void* const* d_in, const int* in_sizes, int n_in,
                              void* d_out, int out_size) {
    const float* data    = (const float*)d_in[0];
    const float* W_exp   = (const float*)d_in[1];
    const float* b_exp   = (const float*)d_in[2];
    const float* W_merge = (const float*)d_in[3];
    float* out = (float*)d_out;
    (void)in_sizes; (void)n_in; (void)out_size;

    cudaFuncSetAttribute(k_mma_sim,     cudaFuncAttributeMaxDynamicSharedMemorySize, SMEM_GE);
    cudaFuncSetAttribute(k_mma_v,       cudaFuncAttributeMaxDynamicSharedMemorySize, SMEM_GE);
    cudaFuncSetAttribute(k_mma_counter, cudaFuncAttributeMaxDynamicSharedMemorySize, SMEM_GE);
    cudaFuncSetAttribute(k_mma_out,     cudaFuncAttributeMaxDynamicSharedMemorySize, SMEM_GE);

    const dim3 tgrid(Nn / 128, Nn / 128, Bb);

    k_prep_data<<<Bb * Nn, 256>>>(data);
    k_prep_pe<<<(Nn * Dd) / 256, 256>>>();
    k_prep_weT<<<dim3(Dd / 32, Dd / 64), dim3(32, 32)>>>(W_exp);
    k_prep_wmT<<<dim3(Dd / 32, (2 * Dd) / 64), dim3(32, 32)>>>(W_merge);

    k_mma_sim<<<dim3(136, 1, Bb), 256, SMEM_GE>>>();
    k_mma_v<<<tgrid, 256, SMEM_GE>>>();
    k_mma_counter<<<tgrid, 256, SMEM_GE>>>(W_exp, b_exp);
    k_mma_out<<<tgrid, 256, SMEM_GE>>>(out);
}

// round 15
// speedup vs baseline: 1.0641x; 1.0285x over previous
#include <cuda_runtime.h>
#include <cuda_fp16.h>
#include <math.h>
#include <stdint.h>

#define Bb 4
#define Nn 2048
#define Dd 2048
typedef __half f16;

// ---- scratch (static __device__; no allocations allowed) ----
__device__ f16 g_cn_hi[(size_t)Bb * Nn * Dd];
__device__ f16 g_dat_hi[(size_t)Bb * Nn * Dd];
__device__ f16 g_sim_hi[(size_t)Bb * Nn * Nn];
__device__ f16 g_pe_hi[(size_t)Nn * Dd];
__device__ f16 g_v_hi[(size_t)Bb * Nn * Nn];
__device__ f16 g_ctr_hi[(size_t)Bb * Nn * Dd];
__device__ f16 g_weT_hi[(size_t)Dd * Dd];
__device__ f16 g_wmT_hi[(size_t)2 * Dd * Dd];
__device__ float g_csum[Bb * Nn];

// =================== helpers ===================

__device__ __forceinline__ void cp16(uint32_t s, const void* g) {
    asm volatile("cp.async.cg.shared.global [%0], [%1], 16;" :: "r"(s), "l"(g));
}
__device__ __forceinline__ void cp_commit() {
    asm volatile("cp.async.commit_group;" ::: "memory");
}
__device__ __forceinline__ void cp_wait2() {
    asm volatile("cp.async.wait_group 2;" ::: "memory");
}

__device__ __forceinline__ void ldsm4(uint32_t& r0, uint32_t& r1, uint32_t& r2,
                                      uint32_t& r3, uint32_t a) {
    asm volatile("ldmatrix.sync.aligned.m8n8.x4.shared.b16 {%0,%1,%2,%3}, [%4];"
                 : "=r"(r0), "=r"(r1), "=r"(r2), "=r"(r3) : "r"(a));
}

__device__ __forceinline__ void mma_f16(float* c, const uint32_t* a, const uint32_t* b) {
    asm volatile("mma.sync.aligned.m16n8k16.row.col.f32.f16.f16.f32 "
                 "{%0,%1,%2,%3}, {%4,%5,%6,%7}, {%8,%9}, {%0,%1,%2,%3};"
                 : "+f"(c[0]), "+f"(c[1]), "+f"(c[2]), "+f"(c[3])
                 : "r"(a[0]), "r"(a[1]), "r"(a[2]), "r"(a[3]), "r"(b[0]), "r"(b[1]));
}

// =================== MMA GEMM core (R12-proven config) ===================
// CTA tile 128(m) x 128(n), K-chunk 32. 8 warps: 4(m) x 2(n) -> warp 32m x 64n.
// 1-pass: 2 tiles/stage (A, B; 8KB each), 4 stages = 64KB -> 2 CTAs/SM.

#define TILE_B   8192
#define NSTAGE   4

// swizzled smem offset within a 128x32-f16 tile (row stride 64B, 4x 16B cols)
__device__ __forceinline__ uint32_t swz(uint32_t row, uint32_t c16) {
    return row * 64u + ((c16 ^ ((row >> 1) & 3u)) << 4);
}

// srcf(kc, P[2], ld[2]): K-major pointers for A, B at this K-chunk
template <typename SrcF>
__device__ __forceinline__ void mma_gemm(int KC, SrcF srcf, float c[2][8][4]) {
    constexpr int STAGE_B = 2 * TILE_B;
    extern __shared__ char smem[];
    const int tid = threadIdx.x;
    const int lane = tid & 31;
    const int wid = tid >> 5;
    const int wm = wid >> 1, wn = wid & 1;
    const uint32_t sbase = (uint32_t)__cvta_generic_to_shared(smem);

    auto load_stage = [&](int kc, int s) {
        const f16* P[2]; int ld[2];
        srcf(kc, P, ld);
        const int row = tid >> 1;
        const int c0 = (tid & 1) * 2;
        #pragma unroll
        for (int t = 0; t < 2; ++t) {
            const f16* src = P[t] + (size_t)row * ld[t] + c0 * 8;
            uint32_t dst = sbase + s * STAGE_B + t * TILE_B;
            cp16(dst + swz(row, c0),     src);
            cp16(dst + swz(row, c0 + 1), src + 8);
        }
    };

    auto compute = [&](int s) {
        const uint32_t base = sbase + s * STAGE_B;
        #pragma unroll
        for (int ks = 0; ks < 2; ++ks) {
            uint32_t a[2][4], bh[8][2];
            #pragma unroll
            for (int mi = 0; mi < 2; ++mi) {
                uint32_t row = wm * 32 + mi * 16 + (lane & 15);
                uint32_t c16 = ks * 2 + (lane >> 4);
                uint32_t off = swz(row, c16);
                ldsm4(a[mi][0], a[mi][1], a[mi][2], a[mi][3], base + off);
            }
            #pragma unroll
            for (int j2 = 0; j2 < 4; ++j2) {
                uint32_t row = wn * 64 + j2 * 16 + ((lane >> 4) << 3) + (lane & 7);
                uint32_t c16 = ks * 2 + ((lane >> 3) & 1);
                uint32_t off = swz(row, c16);
                ldsm4(bh[2 * j2][0], bh[2 * j2][1], bh[2 * j2 + 1][0], bh[2 * j2 + 1][1],
                      base + TILE_B + off);
            }
            #pragma unroll
            for (int mi = 0; mi < 2; ++mi)
                #pragma unroll
                for (int nj = 0; nj < 8; ++nj)
                    mma_f16(c[mi][nj], a[mi], bh[nj]);
        }
    };

    // prefetch 3 stages
    #pragma unroll
    for (int p = 0; p < NSTAGE - 1; ++p) {
        if (p < KC) load_stage(p, p);
        cp_commit();
    }
    for (int kc = 0; kc < KC; ++kc) {
        cp_wait2();
        __syncthreads();
        const int pf = kc + NSTAGE - 1;
        if (pf < KC) load_stage(pf, pf & (NSTAGE - 1));
        cp_commit();
        compute(kc & (NSTAGE - 1));
    }
    __syncthreads();   // smem safe for epilogue reuse
}

// epilogue iteration: calls body(row, col, v0, v1) for each accumulator pair
template <typename BodyF>
__device__ __forceinline__ void epi_loop(int m0, int n0, float c[2][8][4], BodyF body) {
    const int lane = threadIdx.x & 31;
    const int wid = threadIdx.x >> 5;
    const int wm = wid >> 1, wn = wid & 1;
    #pragma unroll
    for (int mi = 0; mi < 2; ++mi)
        #pragma unroll
        for (int nj = 0; nj < 8; ++nj)
            #pragma unroll
            for (int h = 0; h < 2; ++h) {
                const int row = m0 + wm * 32 + mi * 16 + (lane >> 2) + h * 8;
                const int col = n0 + wn * 64 + nj * 8 + (lane & 3) * 2;
                body(row, col, c[mi][nj][2 * h], c[mi][nj][2 * h + 1]);
            }
}

// =================== GEMM kernels ===================

// sim = relu(cn @ cn^T), 1-pass, symmetric: upper-tri tiles only, mirrored
// through padded smem; row sums fused (atomicAdd into g_csum).
// grid.x = 136 (= 16*17/2)
#define EPAD 136
#define SMEM_GE (NSTAGE * 2 * TILE_B)   // 65536
__global__ __launch_bounds__(256, 2) void k_mma_sim() {
    const int b = blockIdx.z;
    int t = blockIdx.x, ti = 0;
    while (t >= 16 - ti) { t -= 16 - ti; ++ti; }
    const int tj = ti + t;
    const int m0 = ti * 128, n0 = tj * 128;

    float c[2][8][4] = {};
    mma_gemm(Dd / 32,
        [&](int kc, const f16** P, int* ld) {
            size_t a = ((size_t)b * Nn + m0) * Dd + kc * 32;
            size_t o = ((size_t)b * Nn + n0) * Dd + kc * 32;
            P[0] = g_cn_hi + a; P[1] = g_cn_hi + o;
            ld[0] = ld[1] = Dd;
        }, c);

    extern __shared__ char smem[];
    f16* sh = (f16*)smem;   // [128][EPAD]
    epi_loop(0, 0, c, [&](int r, int col, float v0, float v1) {
        sh[r * EPAD + col]     = __float2half_rn(fmaxf(v0, 0.f));
        sh[r * EPAD + col + 1] = __float2half_rn(fmaxf(v1, 0.f));
    });
    __syncthreads();

    // write normal orientation
    for (int idx = threadIdx.x; idx < 128 * 16; idx += 256) {
        const int r = idx >> 4, seg = idx & 15;
        size_t o = ((size_t)b * Nn + m0 + r) * Nn + n0 + seg * 8;
        *(uint4*)(g_sim_hi + o) = *(const uint4*)(sh + r * EPAD + seg * 8);
    }
    // mirrored orientation (skip on diagonal tiles)
    if (ti != tj) {
        for (int idx = threadIdx.x; idx < 128 * 16; idx += 256) {
            const int cc = idx >> 4, rseg = idx & 15;
            f16 th[8];
            #pragma unroll
            for (int q = 0; q < 8; ++q)
                th[q] = sh[(rseg * 8 + q) * EPAD + cc];
            size_t o = ((size_t)b * Nn + n0 + cc) * Nn + m0 + rseg * 8;
            *(uint4*)(g_sim_hi + o) = *(const uint4*)th;
        }
    }
    // fused row sums: tid 0-127 -> row-sums into csum[m0+r];
    // tid 128-255 -> mirrored column-sums into csum[n0+c] (off-diagonal only).
    {
        const int tid = threadIdx.x;
        if (tid < 128) {
            float s = 0.f;
            const __half2* rp = (const __half2*)(sh + tid * EPAD);
            #pragma unroll 16
            for (int q = 0; q < 64; ++q) {
                float2 f = __half22float2(rp[q]);
                s += f.x + f.y;
            }
            atomicAdd(&g_csum[b * Nn + m0 + tid], s);
        } else if (ti != tj) {
            const int cc = tid - 128;
            float s2 = 0.f;
            for (int rr = 0; rr < 128; ++rr)
                s2 += __half2float(sh[rr * EPAD + cc]);
            atomicAdd(&g_csum[b * Nn + n0 + cc], s2);
        }
    }
}

// v = posenc @ sim, 1-pass (sim symmetric: B[n][k] = sim[n][k])
__global__ __launch_bounds__(256, 2) void k_mma_v() {
    const int b = blockIdx.z, m0 = blockIdx.y * 128, n0 = blockIdx.x * 128;
    float c[2][8][4] = {};
    mma_gemm(Nn / 32,
        [&](int kc, const f16** P, int* ld) {
            size_t a = (size_t)m0 * Dd + kc * 32;
            size_t o = ((size_t)b * Nn + n0) * Nn + kc * 32;
            P[0] = g_pe_hi + a; P[1] = g_sim_hi + o;
            ld[0] = Dd; ld[1] = Nn;
        }, c);
    epi_loop(m0, n0, c, [&](int row, int col, float v0, float v1) {
        size_t o = ((size_t)b * Nn + row) * Nn + col;
        *(__half2*)(g_v_hi + o) = __half2(__float2half_rn(v0), __float2half_rn(v1));
    });
}

// counter = softplus(v @ W_exp[1:] + csum*W_exp[0] + b_exp), 1-pass
__global__ __launch_bounds__(256, 2) void k_mma_counter(const float* __restrict__ W_exp,
                                                        const float* __restrict__ b_exp) {
    const int b = blockIdx.z, m0 = blockIdx.y * 128, n0 = blockIdx.x * 128;
    float c[2][8][4] = {};
    mma_gemm(Nn / 32,
        [&](int kc, const f16** P, int* ld) {
            size_t a = ((size_t)b * Nn + m0) * Nn + kc * 32;
            size_t o = (size_t)n0 * Dd + kc * 32;
            P[0] = g_v_hi + a; P[1] = g_weT_hi + o;
            ld[0] = Nn; ld[1] = Dd;
        }, c);
    epi_loop(m0, n0, c, [&](int row, int col, float v0, float v1) {
        const float cs = g_csum[b * Nn + row];
        float x0 = v0 + cs * W_exp[col] + b_exp[col];
        float x1 = v1 + cs * W_exp[col + 1] + b_exp[col + 1];
        float s0 = fmaxf(x0, 0.f) + log1pf(expf(-fabsf(x0)));
        float s1 = fmaxf(x1, 0.f) + log1pf(expf(-fabsf(x1)));
        size_t o = ((size_t)b * Nn + row) * Dd + col;
        *(__half2*)(g_ctr_hi + o) = __half2(__float2half_rn(s0), __float2half_rn(s1));
    });
}

// out = data @ W_merge[:D] + counter @ W_merge[D:], 1-pass, fp32 out
__global__ __launch_bounds__(256, 2) void k_mma_out(float* __restrict__ outp) {
    const int b = blockIdx.z, m0 = blockIdx.y * 128, n0 = blockIdx.x * 128;
    float c[2][8][4] = {};
    mma_gemm(2 * Dd / 32,
        [&](int kc, const f16** P, int* ld) {
            if (kc < Dd / 32) {
                size_t a = ((size_t)b * Nn + m0) * Dd + kc * 32;
                size_t o = (size_t)n0 * (2 * Dd) + kc * 32;
                P[0] = g_dat_hi + a; P[1] = g_wmT_hi + o;
            } else {
                size_t a = ((size_t)b * Nn + m0) * Dd + (kc - Dd / 32) * 32;
                size_t o = (size_t)n0 * (2 * Dd) + Dd + (kc - Dd / 32) * 32;
                P[0] = g_ctr_hi + a; P[1] = g_wmT_hi + o;
            }
            ld[0] = Dd; ld[1] = 2 * Dd;
        }, c);
    epi_loop(m0, n0, c, [&](int row, int col, float v0, float v1) {
        size_t o = ((size_t)b * Nn + row) * Dd + col;
        float2 v; v.x = v0; v.y = v1;
        *(float2*)(outp + o) = v;
    });
}

// =================== prep / pointwise kernels ===================

__global__ __launch_bounds__(256) void k_prep_data(const float* __restrict__ data) {
    const int row = blockIdx.x;  // b*Nn + n
    if (threadIdx.x == 0) g_csum[row] = 0.f;   // zero for fused rowsum atomics
    const float4* in4 = (const float4*)(data + (size_t)row * Dd);
    float s = 0.f;
    float4 v[2];
    #pragma unroll
    for (int it = 0; it < 2; ++it) {
        v[it] = in4[threadIdx.x + it * 256];
        s += v[it].x * v[it].x + v[it].y * v[it].y + v[it].z * v[it].z + v[it].w * v[it].w;
    }
    __shared__ float red[32];
    #pragma unroll
    for (int o = 16; o; o >>= 1) s += __shfl_down_sync(0xffffffffu, s, o);
    if ((threadIdx.x & 31) == 0) red[threadIdx.x >> 5] = s;
    __syncthreads();
    if (threadIdx.x < 32) {
        float q = (threadIdx.x < 8) ? red[threadIdx.x] : 0.f;
        #pragma unroll
        for (int o = 4; o; o >>= 1) q += __shfl_down_sync(0xffffffffu, q, o);
        if (threadIdx.x == 0) red[0] = rsqrtf(fmaxf(q, 1e-12f));
    }
    __syncthreads();
    const float r = red[0];
    size_t base4 = (size_t)row * (Dd / 4);   // in units of 4 halves (8B)
    uint2* dat2 = (uint2*)g_dat_hi;
    uint2* cn2  = (uint2*)g_cn_hi;
    #pragma unroll
    for (int it = 0; it < 2; ++it) {
        const int i = threadIdx.x + it * 256;
        __half2 d0 = __floats2half2_rn(v[it].x, v[it].y);
        __half2 d1 = __floats2half2_rn(v[it].z, v[it].w);
        uint2 pd; pd.x = *(uint32_t*)&d0; pd.y = *(uint32_t*)&d1;
        dat2[base4 + i] = pd;
        __half2 c0 = __floats2half2_rn(v[it].x * r, v[it].y * r);
        __half2 c1 = __floats2half2_rn(v[it].z * r, v[it].w * r);
        uint2 pc; pc.x = *(uint32_t*)&c0; pc.y = *(uint32_t*)&c1;
        cn2[base4 + i] = pc;
    }
}

// one thread per (sin,cos) pair: pe[n][2j] = sin(ang), pe[n][2j+1] = cos(ang)
__global__ __launch_bounds__(256) void k_prep_pe() {
    const int p = blockIdx.x * 256 + threadIdx.x;   // over Nn * (Dd/2)
    const int n = p >> 10;                          // Dd/2 = 1024
    const int j = p & 1023;
    const float e = (float)(2 * j) / (float)Dd;
    const float rate = exp2f(-13.28771238f * e);    // 1/10000^e
    const float ang = (float)n * rate;
    float sn, cs;
    sincosf(ang, &sn, &cs);
    __half2 h = __floats2half2_rn(sn, cs);
    *(__half2*)(g_pe_hi + (size_t)n * Dd + 2 * j) = h;
}

// W_expT[n][k] = W_exp[(k+1)*Dd + n]. Tile 64k x 32n; half2 writes (128B/warp).
__global__ void k_prep_weT(const float* __restrict__ W_exp) {
    __shared__ float t[32][65];   // [n][k]
    const int n0 = blockIdx.x * 32;
    const int k0 = blockIdx.y * 64;
    #pragma unroll
    for (int i = 0; i < 2; ++i) {
        int k = 2 * threadIdx.y + i;
        t[threadIdx.x][k] = W_exp[(size_t)(k0 + k + 1) * Dd + n0 + threadIdx.x];
    }
    __syncthreads();
    const int n = threadIdx.y;
    const int kk = 2 * threadIdx.x;
    __half2 h = __floats2half2_rn(t[n][kk], t[n][kk + 1]);
    *(__half2*)(g_weT_hi + (size_t)(n0 + n) * Dd + k0 + kk) = h;
}

// W_mergeT[n][k] = W_merge[k*Dd + n], k in [0,4096). Tile 64k x 32n.
__global__ void k_prep_wmT(const float* __restrict__ W_merge) {
    __shared__ float t[32][65];   // [n][k]
    const int n0 = blockIdx.x * 32;
    const int k0 = blockIdx.y * 64;
    #pragma unroll
    for (int i = 0; i < 2; ++i) {
        int k = 2 * threadIdx.y + i;
        t[threadIdx.x][k] = W_merge[(size_t)(k0 + k) * Dd + n0 + threadIdx.x];
    }
    __syncthreads();
    const int n = threadIdx.y;
    const int kk = 2 * threadIdx.x;
    __half2 h = __floats2half2_rn(t[n][kk], t[n][kk + 1]);
    *(__half2*)(g_wmT_hi + (size_t)(n0 + n) * (2 * Dd) + k0 + kk) = h;
}

// =================== launch ===================

extern "C" void kernel_launch(void* const* d_in, const int* in_sizes, int n_in,
                              void* d_out, int out_size) {
    const float* data    = (const float*)d_in[0];
    const float* W_exp   = (const float*)d_in[1];
    const float* b_exp   = (const float*)d_in[2];
    const float* W_merge = (const float*)d_in[3];
    float* out = (float*)d_out;
    (void)in_sizes; (void)n_in; (void)out_size;

    cudaFuncSetAttribute(k_mma_sim,     cudaFuncAttributeMaxDynamicSharedMemorySize, SMEM_GE);
    cudaFuncSetAttribute(k_mma_v,       cudaFuncAttributeMaxDynamicSharedMemorySize, SMEM_GE);
    cudaFuncSetAttribute(k_mma_counter, cudaFuncAttributeMaxDynamicSharedMemorySize, SMEM_GE);
    cudaFuncSetAttribute(k_mma_out,     cudaFuncAttributeMaxDynamicSharedMemorySize, SMEM_GE);

    const dim3 tgrid(Nn / 128, Nn / 128, Bb);

    k_prep_data<<<Bb * Nn, 256>>>(data);
    k_prep_pe<<<(Nn * (Dd / 2)) / 256, 256>>>();
    k_prep_weT<<<dim3(Dd / 32, Dd / 64), dim3(32, 32)>>>(W_exp);
    k_prep_wmT<<<dim3(Dd / 32, (2 * Dd) / 64), dim3(32, 32)>>>(W_merge);

    k_mma_sim<<<dim3(136, 1, Bb), 256, SMEM_GE>>>();
    k_mma_v<<<tgrid, 256, SMEM_GE>>>();
    k_mma_counter<<<tgrid, 256, SMEM_GE>>>(W_exp, b_exp);
    k_mma_out<<<tgrid, 256, SMEM_GE>>>(out);
}

// round 16
// speedup vs baseline: 1.0738x; 1.0091x over previous
#include <cuda_runtime.h>
#include <cuda_fp16.h>
#include <math.h>
#include <stdint.h>

#define Bb 4
#define Nn 2048
#define Dd 2048
typedef __half f16;

// ---- scratch (static __device__; no allocations allowed) ----
__device__ f16 g_cn_hi[(size_t)Bb * Nn * Dd];
__device__ f16 g_dat_hi[(size_t)Bb * Nn * Dd];
__device__ f16 g_sim_hi[(size_t)Bb * Nn * Nn];
__device__ f16 g_pe_hi[(size_t)Nn * Dd];
__device__ f16 g_v_hi[(size_t)Bb * Nn * Nn];
__device__ f16 g_ctr_hi[(size_t)Bb * Nn * Dd];
__device__ f16 g_weT_hi[(size_t)Dd * Dd];
__device__ f16 g_wmT_hi[(size_t)2 * Dd * Dd];
__device__ float g_csum[Bb * Nn];

// =================== helpers ===================

__device__ __forceinline__ void cp16(uint32_t s, const void* g) {
    asm volatile("cp.async.cg.shared.global [%0], [%1], 16;" :: "r"(s), "l"(g));
}
__device__ __forceinline__ void cp_commit() {
    asm volatile("cp.async.commit_group;" ::: "memory");
}
__device__ __forceinline__ void cp_wait2() {
    asm volatile("cp.async.wait_group 2;" ::: "memory");
}

__device__ __forceinline__ void ldsm4(uint32_t& r0, uint32_t& r1, uint32_t& r2,
                                      uint32_t& r3, uint32_t a) {
    asm volatile("ldmatrix.sync.aligned.m8n8.x4.shared.b16 {%0,%1,%2,%3}, [%4];"
                 : "=r"(r0), "=r"(r1), "=r"(r2), "=r"(r3) : "r"(a));
}

__device__ __forceinline__ void mma_f16(float* c, const uint32_t* a, const uint32_t* b) {
    asm volatile("mma.sync.aligned.m16n8k16.row.col.f32.f16.f16.f32 "
                 "{%0,%1,%2,%3}, {%4,%5,%6,%7}, {%8,%9}, {%0,%1,%2,%3};"
                 : "+f"(c[0]), "+f"(c[1]), "+f"(c[2]), "+f"(c[3])
                 : "r"(a[0]), "r"(a[1]), "r"(a[2]), "r"(a[3]), "r"(b[0]), "r"(b[1]));
}

// =================== MMA GEMM core (R12-proven config) ===================
// CTA tile 128(m) x 128(n), K-chunk 32. 8 warps: 4(m) x 2(n) -> warp 32m x 64n.
// 1-pass: 2 tiles/stage (A, B; 8KB each), 4 stages = 64KB -> 2 CTAs/SM.

#define TILE_B   8192
#define NSTAGE   4

// swizzled smem offset within a 128x32-f16 tile (row stride 64B, 4x 16B cols)
__device__ __forceinline__ uint32_t swz(uint32_t row, uint32_t c16) {
    return row * 64u + ((c16 ^ ((row >> 1) & 3u)) << 4);
}

// srcf(kc, P[2], ld[2]): K-major pointers for A, B at this K-chunk
template <typename SrcF>
__device__ __forceinline__ void mma_gemm(int KC, SrcF srcf, float c[2][8][4]) {
    constexpr int STAGE_B = 2 * TILE_B;
    extern __shared__ char smem[];
    const int tid = threadIdx.x;
    const int lane = tid & 31;
    const int wid = tid >> 5;
    const int wm = wid >> 1, wn = wid & 1;
    const uint32_t sbase = (uint32_t)__cvta_generic_to_shared(smem);

    auto load_stage = [&](int kc, int s) {
        const f16* P[2]; int ld[2];
        srcf(kc, P, ld);
        const int row = tid >> 1;
        const int c0 = (tid & 1) * 2;
        #pragma unroll
        for (int t = 0; t < 2; ++t) {
            const f16* src = P[t] + (size_t)row * ld[t] + c0 * 8;
            uint32_t dst = sbase + s * STAGE_B + t * TILE_B;
            cp16(dst + swz(row, c0),     src);
            cp16(dst + swz(row, c0 + 1), src + 8);
        }
    };

    auto compute = [&](int s) {
        const uint32_t base = sbase + s * STAGE_B;
        #pragma unroll
        for (int ks = 0; ks < 2; ++ks) {
            uint32_t a[2][4], bh[8][2];
            #pragma unroll
            for (int mi = 0; mi < 2; ++mi) {
                uint32_t row = wm * 32 + mi * 16 + (lane & 15);
                uint32_t c16 = ks * 2 + (lane >> 4);
                uint32_t off = swz(row, c16);
                ldsm4(a[mi][0], a[mi][1], a[mi][2], a[mi][3], base + off);
            }
            #pragma unroll
            for (int j2 = 0; j2 < 4; ++j2) {
                uint32_t row = wn * 64 + j2 * 16 + ((lane >> 4) << 3) + (lane & 7);
                uint32_t c16 = ks * 2 + ((lane >> 3) & 1);
                uint32_t off = swz(row, c16);
                ldsm4(bh[2 * j2][0], bh[2 * j2][1], bh[2 * j2 + 1][0], bh[2 * j2 + 1][1],
                      base + TILE_B + off);
            }
            #pragma unroll
            for (int mi = 0; mi < 2; ++mi)
                #pragma unroll
                for (int nj = 0; nj < 8; ++nj)
                    mma_f16(c[mi][nj], a[mi], bh[nj]);
        }
    };

    // prefetch 3 stages
    #pragma unroll
    for (int p = 0; p < NSTAGE - 1; ++p) {
        if (p < KC) load_stage(p, p);
        cp_commit();
    }
    for (int kc = 0; kc < KC; ++kc) {
        cp_wait2();
        __syncthreads();
        const int pf = kc + NSTAGE - 1;
        if (pf < KC) load_stage(pf, pf & (NSTAGE - 1));
        cp_commit();
        compute(kc & (NSTAGE - 1));
    }
    __syncthreads();   // smem safe for epilogue reuse
}

// epilogue iteration: calls body(row, col, v0, v1) for each accumulator pair
template <typename BodyF>
__device__ __forceinline__ void epi_loop(int m0, int n0, float c[2][8][4], BodyF body) {
    const int lane = threadIdx.x & 31;
    const int wid = threadIdx.x >> 5;
    const int wm = wid >> 1, wn = wid & 1;
    #pragma unroll
    for (int mi = 0; mi < 2; ++mi)
        #pragma unroll
        for (int nj = 0; nj < 8; ++nj)
            #pragma unroll
            for (int h = 0; h < 2; ++h) {
                const int row = m0 + wm * 32 + mi * 16 + (lane >> 2) + h * 8;
                const int col = n0 + wn * 64 + nj * 8 + (lane & 3) * 2;
                body(row, col, c[mi][nj][2 * h], c[mi][nj][2 * h + 1]);
            }
}

#define EPAD 136

// coalesced copy of staged 128x128 f16 tile -> gmem rows (uint4 = 8 halves)
__device__ __forceinline__ void store_tile_coalesced(const f16* sh, f16* dst_base,
                                                     int m0, int n0, int ld) {
    for (int idx = threadIdx.x; idx < 128 * 16; idx += 256) {
        const int r = idx >> 4, seg = idx & 15;
        size_t o = (size_t)(m0 + r) * ld + n0 + seg * 8;
        *(uint4*)(dst_base + o) = *(const uint4*)(sh + r * EPAD + seg * 8);
    }
}

// =================== GEMM kernels ===================

// sim = relu(cn @ cn^T), 1-pass, symmetric: upper-tri tiles only, mirrored
// through padded smem; row sums fused (atomicAdd into g_csum).
// grid.x = 136 (= 16*17/2)
#define SMEM_GE (NSTAGE * 2 * TILE_B)   // 65536
__global__ __launch_bounds__(256, 2) void k_mma_sim() {
    const int b = blockIdx.z;
    int t = blockIdx.x, ti = 0;
    while (t >= 16 - ti) { t -= 16 - ti; ++ti; }
    const int tj = ti + t;
    const int m0 = ti * 128, n0 = tj * 128;

    float c[2][8][4] = {};
    mma_gemm(Dd / 32,
        [&](int kc, const f16** P, int* ld) {
            size_t a = ((size_t)b * Nn + m0) * Dd + kc * 32;
            size_t o = ((size_t)b * Nn + n0) * Dd + kc * 32;
            P[0] = g_cn_hi + a; P[1] = g_cn_hi + o;
            ld[0] = ld[1] = Dd;
        }, c);

    extern __shared__ char smem[];
    f16* sh = (f16*)smem;   // [128][EPAD]
    epi_loop(0, 0, c, [&](int r, int col, float v0, float v1) {
        sh[r * EPAD + col]     = __float2half_rn(fmaxf(v0, 0.f));
        sh[r * EPAD + col + 1] = __float2half_rn(fmaxf(v1, 0.f));
    });
    __syncthreads();

    // write normal orientation
    store_tile_coalesced(sh, g_sim_hi + (size_t)b * Nn * Nn, m0, n0, Nn);
    // mirrored orientation (skip on diagonal tiles)
    if (ti != tj) {
        for (int idx = threadIdx.x; idx < 128 * 16; idx += 256) {
            const int cc = idx >> 4, rseg = idx & 15;
            f16 th[8];
            #pragma unroll
            for (int q = 0; q < 8; ++q)
                th[q] = sh[(rseg * 8 + q) * EPAD + cc];
            size_t o = ((size_t)b * Nn + n0 + cc) * Nn + m0 + rseg * 8;
            *(uint4*)(g_sim_hi + o) = *(const uint4*)th;
        }
    }
    // fused row sums: tid 0-127 -> row-sums into csum[m0+r];
    // tid 128-255 -> mirrored column-sums into csum[n0+c] (off-diagonal only).
    {
        const int tid = threadIdx.x;
        if (tid < 128) {
            float s = 0.f;
            const __half2* rp = (const __half2*)(sh + tid * EPAD);
            #pragma unroll 16
            for (int q = 0; q < 64; ++q) {
                float2 f = __half22float2(rp[q]);
                s += f.x + f.y;
            }
            atomicAdd(&g_csum[b * Nn + m0 + tid], s);
        } else if (ti != tj) {
            const int cc = tid - 128;
            float s2 = 0.f;
            for (int rr = 0; rr < 128; ++rr)
                s2 += __half2float(sh[rr * EPAD + cc]);
            atomicAdd(&g_csum[b * Nn + n0 + cc], s2);
        }
    }
}

// v = posenc @ sim, 1-pass (sim symmetric: B[n][k] = sim[n][k]); staged epilogue
__global__ __launch_bounds__(256, 2) void k_mma_v() {
    const int b = blockIdx.z, m0 = blockIdx.y * 128, n0 = blockIdx.x * 128;
    float c[2][8][4] = {};
    mma_gemm(Nn / 32,
        [&](int kc, const f16** P, int* ld) {
            size_t a = (size_t)m0 * Dd + kc * 32;
            size_t o = ((size_t)b * Nn + n0) * Nn + kc * 32;
            P[0] = g_pe_hi + a; P[1] = g_sim_hi + o;
            ld[0] = Dd; ld[1] = Nn;
        }, c);
    extern __shared__ char smem[];
    f16* sh = (f16*)smem;   // [128][EPAD]
    epi_loop(0, 0, c, [&](int r, int col, float v0, float v1) {
        sh[r * EPAD + col]     = __float2half_rn(v0);
        sh[r * EPAD + col + 1] = __float2half_rn(v1);
    });
    __syncthreads();
    store_tile_coalesced(sh, g_v_hi + (size_t)b * Nn * Nn, m0, n0, Nn);
}

// counter = softplus(v @ W_exp[1:] + csum*W_exp[0] + b_exp); staged epilogue
__global__ __launch_bounds__(256, 2) void k_mma_counter(const float* __restrict__ W_exp,
                                                        const float* __restrict__ b_exp) {
    const int b = blockIdx.z, m0 = blockIdx.y * 128, n0 = blockIdx.x * 128;
    float c[2][8][4] = {};
    mma_gemm(Nn / 32,
        [&](int kc, const f16** P, int* ld) {
            size_t a = ((size_t)b * Nn + m0) * Nn + kc * 32;
            size_t o = (size_t)n0 * Dd + kc * 32;
            P[0] = g_v_hi + a; P[1] = g_weT_hi + o;
            ld[0] = Nn; ld[1] = Dd;
        }, c);
    extern __shared__ char smem[];
    f16* sh = (f16*)smem;   // [128][EPAD]
    epi_loop(0, 0, c, [&](int r, int lcol, float v0, float v1) {
        const float cs = g_csum[b * Nn + m0 + r];
        const int col = n0 + lcol;
        float x0 = v0 + cs * W_exp[col] + b_exp[col];
        float x1 = v1 + cs * W_exp[col + 1] + b_exp[col + 1];
        float s0 = fmaxf(x0, 0.f) + log1pf(expf(-fabsf(x0)));
        float s1 = fmaxf(x1, 0.f) + log1pf(expf(-fabsf(x1)));
        sh[r * EPAD + lcol]     = __float2half_rn(s0);
        sh[r * EPAD + lcol + 1] = __float2half_rn(s1);
    });
    __syncthreads();
    store_tile_coalesced(sh, g_ctr_hi + (size_t)b * Nn * Dd, m0, n0, Dd);
}

// out = data @ W_merge[:D] + counter @ W_merge[D:], 1-pass, fp32 out
// (float2 stores already fill 32B sectors; no staging needed)
__global__ __launch_bounds__(256, 2) void k_mma_out(float* __restrict__ outp) {
    const int b = blockIdx.z, m0 = blockIdx.y * 128, n0 = blockIdx.x * 128;
    float c[2][8][4] = {};
    mma_gemm(2 * Dd / 32,
        [&](int kc, const f16** P, int* ld) {
            if (kc < Dd / 32) {
                size_t a = ((size_t)b * Nn + m0) * Dd + kc * 32;
                size_t o = (size_t)n0 * (2 * Dd) + kc * 32;
                P[0] = g_dat_hi + a; P[1] = g_wmT_hi + o;
            } else {
                size_t a = ((size_t)b * Nn + m0) * Dd + (kc - Dd / 32) * 32;
                size_t o = (size_t)n0 * (2 * Dd) + Dd + (kc - Dd / 32) * 32;
                P[0] = g_ctr_hi + a; P[1] = g_wmT_hi + o;
            }
            ld[0] = Dd; ld[1] = 2 * Dd;
        }, c);
    epi_loop(m0, n0, c, [&](int row, int col, float v0, float v1) {
        size_t o = ((size_t)b * Nn + row) * Dd + col;
        float2 v; v.x = v0; v.y = v1;
        *(float2*)(outp + o) = v;
    });
}

// =================== prep / pointwise kernels ===================

__global__ __launch_bounds__(256) void k_prep_data(const float* __restrict__ data) {
    const int row = blockIdx.x;  // b*Nn + n
    if (threadIdx.x == 0) g_csum[row] = 0.f;   // zero for fused rowsum atomics
    const float4* in4 = (const float4*)(data + (size_t)row * Dd);
    float s = 0.f;
    float4 v[2];
    #pragma unroll
    for (int it = 0; it < 2; ++it) {
        v[it] = in4[threadIdx.x + it * 256];
        s += v[it].x * v[it].x + v[it].y * v[it].y + v[it].z * v[it].z + v[it].w * v[it].w;
    }
    __shared__ float red[32];
    #pragma unroll
    for (int o = 16; o; o >>= 1) s += __shfl_down_sync(0xffffffffu, s, o);
    if ((threadIdx.x & 31) == 0) red[threadIdx.x >> 5] = s;
    __syncthreads();
    if (threadIdx.x < 32) {
        float q = (threadIdx.x < 8) ? red[threadIdx.x] : 0.f;
        #pragma unroll
        for (int o = 4; o; o >>= 1) q += __shfl_down_sync(0xffffffffu, q, o);
        if (threadIdx.x == 0) red[0] = rsqrtf(fmaxf(q, 1e-12f));
    }
    __syncthreads();
    const float r = red[0];
    size_t base4 = (size_t)row * (Dd / 4);   // in units of 4 halves (8B)
    uint2* dat2 = (uint2*)g_dat_hi;
    uint2* cn2  = (uint2*)g_cn_hi;
    #pragma unroll
    for (int it = 0; it < 2; ++it) {
        const int i = threadIdx.x + it * 256;
        __half2 d0 = __floats2half2_rn(v[it].x, v[it].y);
        __half2 d1 = __floats2half2_rn(v[it].z, v[it].w);
        uint2 pd; pd.x = *(uint32_t*)&d0; pd.y = *(uint32_t*)&d1;
        dat2[base4 + i] = pd;
        __half2 c0 = __floats2half2_rn(v[it].x * r, v[it].y * r);
        __half2 c1 = __floats2half2_rn(v[it].z * r, v[it].w * r);
        uint2 pc; pc.x = *(uint32_t*)&c0; pc.y = *(uint32_t*)&c1;
        cn2[base4 + i] = pc;
    }
}

// one thread per (sin,cos) pair: pe[n][2j] = sin(ang), pe[n][2j+1] = cos(ang)
__global__ __launch_bounds__(256) void k_prep_pe() {
    const int p = blockIdx.x * 256 + threadIdx.x;   // over Nn * (Dd/2)
    const int n = p >> 10;                          // Dd/2 = 1024
    const int j = p & 1023;
    const float e = (float)(2 * j) / (float)Dd;
    const float rate = exp2f(-13.28771238f * e);    // 1/10000^e
    const float ang = (float)n * rate;
    float sn, cs;
    sincosf(ang, &sn, &cs);
    __half2 h = __floats2half2_rn(sn, cs);
    *(__half2*)(g_pe_hi + (size_t)n * Dd + 2 * j) = h;
}

// W_expT[n][k] = W_exp[(k+1)*Dd + n]. Tile 64k x 32n; half2 writes (128B/warp).
__global__ void k_prep_weT(const float* __restrict__ W_exp) {
    __shared__ float t[32][65];   // [n][k]
    const int n0 = blockIdx.x * 32;
    const int k0 = blockIdx.y * 64;
    #pragma unroll
    for (int i = 0; i < 2; ++i) {
        int k = 2 * threadIdx.y + i;
        t[threadIdx.x][k] = W_exp[(size_t)(k0 + k + 1) * Dd + n0 + threadIdx.x];
    }
    __syncthreads();
    const int n = threadIdx.y;
    const int kk = 2 * threadIdx.x;
    __half2 h = __floats2half2_rn(t[n][kk], t[n][kk + 1]);
    *(__half2*)(g_weT_hi + (size_t)(n0 + n) * Dd + k0 + kk) = h;
}

// W_mergeT[n][k] = W_merge[k*Dd + n], k in [0,4096). Tile 64k x 32n.
__global__ void k_prep_wmT(const float* __restrict__ W_merge) {
    __shared__ float t[32][65];   // [n][k]
    const int n0 = blockIdx.x * 32;
    const int k0 = blockIdx.y * 64;
    #pragma unroll
    for (int i = 0; i < 2; ++i) {
        int k = 2 * threadIdx.y + i;
        t[threadIdx.x][k] = W_merge[(size_t)(k0 + k) * Dd + n0 + threadIdx.x];
    }
    __syncthreads();
    const int n = threadIdx.y;
    const int kk = 2 * threadIdx.x;
    __half2 h = __floats2half2_rn(t[n][kk], t[n][kk + 1]);
    *(__half2*)(g_wmT_hi + (size_t)(n0 + n) * (2 * Dd) + k0 + kk) = h;
}

// =================== launch ===================

extern "C" void kernel_launch(void* const* d_in, const int* in_sizes, int n_in,
                              void* d_out, int out_size) {
    const float* data    = (const float*)d_in[0];
    const float* W_exp   = (const float*)d_in[1];
    const float* b_exp   = (const float*)d_in[2];
    const float* W_merge = (const float*)d_in[3];
    float* out = (float*)d_out;
    (void)in_sizes; (void)n_in; (void)out_size;

    cudaFuncSetAttribute(k_mma_sim,     cudaFuncAttributeMaxDynamicSharedMemorySize, SMEM_GE);
    cudaFuncSetAttribute(k_mma_v,       cudaFuncAttributeMaxDynamicSharedMemorySize, SMEM_GE);
    cudaFuncSetAttribute(k_mma_counter, cudaFuncAttributeMaxDynamicSharedMemorySize, SMEM_GE);
    cudaFuncSetAttribute(k_mma_out,     cudaFuncAttributeMaxDynamicSharedMemorySize, SMEM_GE);

    const dim3 tgrid(Nn / 128, Nn / 128, Bb);

    k_prep_data<<<Bb * Nn, 256>>>(data);
    k_prep_pe<<<(Nn * (Dd / 2)) / 256, 256>>>();
    k_prep_weT<<<dim3(Dd / 32, Dd / 64), dim3(32, 32)>>>(W_exp);
    k_prep_wmT<<<dim3(Dd / 32, (2 * Dd) / 64), dim3(32, 32)>>>(W_merge);

    k_mma_sim<<<dim3(136, 1, Bb), 256, SMEM_GE>>>();
    k_mma_v<<<tgrid, 256, SMEM_GE>>>();
    k_mma_counter<<<tgrid, 256, SMEM_GE>>>(W_exp, b_exp);
    k_mma_out<<<tgrid, 256, SMEM_GE>>>(out);
}

// round 17
// speedup vs baseline: 1.0938x; 1.0186x over previous
#include <cuda_runtime.h>
#include <cuda_fp16.h>
#include <math.h>
#include <stdint.h>

#define Bb 4
#define Nn 2048
#define Dd 2048
typedef __half f16;

// ---- scratch (static __device__; no allocations allowed) ----
__device__ f16 g_cn_hi[(size_t)Bb * Nn * Dd];
__device__ f16 g_dat_hi[(size_t)Bb * Nn * Dd];
__device__ f16 g_sim_hi[(size_t)Bb * Nn * Nn];
__device__ f16 g_pe_hi[(size_t)Nn * Dd];
__device__ f16 g_v_hi[(size_t)Bb * Nn * Nn];
__device__ f16 g_ctr_hi[(size_t)Bb * Nn * Dd];
__device__ f16 g_weT_hi[(size_t)Dd * Dd];
__device__ f16 g_wmT_hi[(size_t)2 * Dd * Dd];
__device__ float g_csum[Bb * Nn];

// =================== helpers ===================

__device__ __forceinline__ void cp16(uint32_t s, const void* g) {
    asm volatile("cp.async.cg.shared.global [%0], [%1], 16;" :: "r"(s), "l"(g));
}
__device__ __forceinline__ void cp_commit() {
    asm volatile("cp.async.commit_group;" ::: "memory");
}
__device__ __forceinline__ void cp_wait2() {
    asm volatile("cp.async.wait_group 2;" ::: "memory");
}

__device__ __forceinline__ void ldsm4(uint32_t& r0, uint32_t& r1, uint32_t& r2,
                                      uint32_t& r3, uint32_t a) {
    asm volatile("ldmatrix.sync.aligned.m8n8.x4.shared.b16 {%0,%1,%2,%3}, [%4];"
                 : "=r"(r0), "=r"(r1), "=r"(r2), "=r"(r3) : "r"(a));
}

__device__ __forceinline__ void mma_f16(float* c, const uint32_t* a, const uint32_t* b) {
    asm volatile("mma.sync.aligned.m16n8k16.row.col.f32.f16.f16.f32 "
                 "{%0,%1,%2,%3}, {%4,%5,%6,%7}, {%8,%9}, {%0,%1,%2,%3};"
                 : "+f"(c[0]), "+f"(c[1]), "+f"(c[2]), "+f"(c[3])
                 : "r"(a[0]), "r"(a[1]), "r"(a[2]), "r"(a[3]), "r"(b[0]), "r"(b[1]));
}

// =================== MMA GEMM core (R12-proven config) ===================
// CTA tile 128(m) x 128(n), K-chunk 32. 8 warps: 4(m) x 2(n) -> warp 32m x 64n.
// 1-pass: 2 tiles/stage (A, B; 8KB each), 4 stages = 64KB -> 2 CTAs/SM.

#define TILE_B   8192
#define NSTAGE   4

// swizzled smem offset within a 128x32-f16 tile (row stride 64B, 4x 16B cols)
__device__ __forceinline__ uint32_t swz(uint32_t row, uint32_t c16) {
    return row * 64u + ((c16 ^ ((row >> 1) & 3u)) << 4);
}

// srcf(kc, P[2], ld[2]): K-major pointers for A, B at this K-chunk
template <typename SrcF>
__device__ __forceinline__ void mma_gemm(int KC, SrcF srcf, float c[2][8][4]) {
    constexpr int STAGE_B = 2 * TILE_B;
    extern __shared__ char smem[];
    const int tid = threadIdx.x;
    const int lane = tid & 31;
    const int wid = tid >> 5;
    const int wm = wid >> 1, wn = wid & 1;
    const uint32_t sbase = (uint32_t)__cvta_generic_to_shared(smem);

    auto load_stage = [&](int kc, int s) {
        const f16* P[2]; int ld[2];
        srcf(kc, P, ld);
        const int row = tid >> 1;
        const int c0 = (tid & 1) * 2;
        #pragma unroll
        for (int t = 0; t < 2; ++t) {
            const f16* src = P[t] + (size_t)row * ld[t] + c0 * 8;
            uint32_t dst = sbase + s * STAGE_B + t * TILE_B;
            cp16(dst + swz(row, c0),     src);
            cp16(dst + swz(row, c0 + 1), src + 8);
        }
    };

    auto compute = [&](int s) {
        const uint32_t base = sbase + s * STAGE_B;
        #pragma unroll
        for (int ks = 0; ks < 2; ++ks) {
            uint32_t a[2][4], bh[8][2];
            #pragma unroll
            for (int mi = 0; mi < 2; ++mi) {
                uint32_t row = wm * 32 + mi * 16 + (lane & 15);
                uint32_t c16 = ks * 2 + (lane >> 4);
                uint32_t off = swz(row, c16);
                ldsm4(a[mi][0], a[mi][1], a[mi][2], a[mi][3], base + off);
            }
            #pragma unroll
            for (int j2 = 0; j2 < 4; ++j2) {
                uint32_t row = wn * 64 + j2 * 16 + ((lane >> 4) << 3) + (lane & 7);
                uint32_t c16 = ks * 2 + ((lane >> 3) & 1);
                uint32_t off = swz(row, c16);
                ldsm4(bh[2 * j2][0], bh[2 * j2][1], bh[2 * j2 + 1][0], bh[2 * j2 + 1][1],
                      base + TILE_B + off);
            }
            #pragma unroll
            for (int mi = 0; mi < 2; ++mi)
                #pragma unroll
                for (int nj = 0; nj < 8; ++nj)
                    mma_f16(c[mi][nj], a[mi], bh[nj]);
        }
    };

    // prefetch 3 stages
    #pragma unroll
    for (int p = 0; p < NSTAGE - 1; ++p) {
        if (p < KC) load_stage(p, p);
        cp_commit();
    }
    for (int kc = 0; kc < KC; ++kc) {
        cp_wait2();
        __syncthreads();
        const int pf = kc + NSTAGE - 1;
        if (pf < KC) load_stage(pf, pf & (NSTAGE - 1));
        cp_commit();
        compute(kc & (NSTAGE - 1));
    }
    __syncthreads();   // smem safe for epilogue reuse
}

// epilogue iteration: calls body(row, col, v0, v1) for each accumulator pair
template <typename BodyF>
__device__ __forceinline__ void epi_loop(int m0, int n0, float c[2][8][4], BodyF body) {
    const int lane = threadIdx.x & 31;
    const int wid = threadIdx.x >> 5;
    const int wm = wid >> 1, wn = wid & 1;
    #pragma unroll
    for (int mi = 0; mi < 2; ++mi)
        #pragma unroll
        for (int nj = 0; nj < 8; ++nj)
            #pragma unroll
            for (int h = 0; h < 2; ++h) {
                const int row = m0 + wm * 32 + mi * 16 + (lane >> 2) + h * 8;
                const int col = n0 + wn * 64 + nj * 8 + (lane & 3) * 2;
                body(row, col, c[mi][nj][2 * h], c[mi][nj][2 * h + 1]);
            }
}

#define EPAD 136

// coalesced copy of staged 128x128 f16 tile -> gmem rows (uint4 = 8 halves)
__device__ __forceinline__ void store_tile_coalesced(const f16* sh, f16* dst_base,
                                                     int m0, int n0, int ld) {
    for (int idx = threadIdx.x; idx < 128 * 16; idx += 256) {
        const int r = idx >> 4, seg = idx & 15;
        size_t o = (size_t)(m0 + r) * ld + n0 + seg * 8;
        *(uint4*)(dst_base + o) = *(const uint4*)(sh + r * EPAD + seg * 8);
    }
}

// =================== GEMM kernels ===================

// sim = relu(cn @ cn^T), 1-pass, symmetric: upper-tri tiles only, mirrored
// through padded smem; row sums fused (atomicAdd into g_csum).
// grid.x = 136 (= 16*17/2)
#define SMEM_GE (NSTAGE * 2 * TILE_B)   // 65536
__global__ __launch_bounds__(256, 2) void k_mma_sim() {
    const int b = blockIdx.z;
    int t = blockIdx.x, ti = 0;
    while (t >= 16 - ti) { t -= 16 - ti; ++ti; }
    const int tj = ti + t;
    const int m0 = ti * 128, n0 = tj * 128;

    float c[2][8][4] = {};
    mma_gemm(Dd / 32,
        [&](int kc, const f16** P, int* ld) {
            size_t a = ((size_t)b * Nn + m0) * Dd + kc * 32;
            size_t o = ((size_t)b * Nn + n0) * Dd + kc * 32;
            P[0] = g_cn_hi + a; P[1] = g_cn_hi + o;
            ld[0] = ld[1] = Dd;
        }, c);

    extern __shared__ char smem[];
    f16* sh = (f16*)smem;   // [128][EPAD]
    epi_loop(0, 0, c, [&](int r, int col, float v0, float v1) {
        sh[r * EPAD + col]     = __float2half_rn(fmaxf(v0, 0.f));
        sh[r * EPAD + col + 1] = __float2half_rn(fmaxf(v1, 0.f));
    });
    __syncthreads();

    // write normal orientation
    store_tile_coalesced(sh, g_sim_hi + (size_t)b * Nn * Nn, m0, n0, Nn);
    // mirrored orientation (skip on diagonal tiles)
    if (ti != tj) {
        for (int idx = threadIdx.x; idx < 128 * 16; idx += 256) {
            const int cc = idx >> 4, rseg = idx & 15;
            f16 th[8];
            #pragma unroll
            for (int q = 0; q < 8; ++q)
                th[q] = sh[(rseg * 8 + q) * EPAD + cc];
            size_t o = ((size_t)b * Nn + n0 + cc) * Nn + m0 + rseg * 8;
            *(uint4*)(g_sim_hi + o) = *(const uint4*)th;
        }
    }
    // fused row sums: tid 0-127 -> row-sums into csum[m0+r];
    // tid 128-255 -> mirrored column-sums into csum[n0+c] (off-diagonal only).
    {
        const int tid = threadIdx.x;
        if (tid < 128) {
            float s = 0.f;
            const __half2* rp = (const __half2*)(sh + tid * EPAD);
            #pragma unroll 16
            for (int q = 0; q < 64; ++q) {
                float2 f = __half22float2(rp[q]);
                s += f.x + f.y;
            }
            atomicAdd(&g_csum[b * Nn + m0 + tid], s);
        } else if (ti != tj) {
            const int cc = tid - 128;
            float s2 = 0.f;
            for (int rr = 0; rr < 128; ++rr)
                s2 += __half2float(sh[rr * EPAD + cc]);
            atomicAdd(&g_csum[b * Nn + n0 + cc], s2);
        }
    }
}

// v = posenc @ sim, 1-pass (sim symmetric: B[n][k] = sim[n][k]); staged epilogue
__global__ __launch_bounds__(256, 2) void k_mma_v() {
    const int b = blockIdx.z, m0 = blockIdx.y * 128, n0 = blockIdx.x * 128;
    float c[2][8][4] = {};
    mma_gemm(Nn / 32,
        [&](int kc, const f16** P, int* ld) {
            size_t a = (size_t)m0 * Dd + kc * 32;
            size_t o = ((size_t)b * Nn + n0) * Nn + kc * 32;
            P[0] = g_pe_hi + a; P[1] = g_sim_hi + o;
            ld[0] = Dd; ld[1] = Nn;
        }, c);
    extern __shared__ char smem[];
    f16* sh = (f16*)smem;   // [128][EPAD]
    epi_loop(0, 0, c, [&](int r, int col, float v0, float v1) {
        sh[r * EPAD + col]     = __float2half_rn(v0);
        sh[r * EPAD + col + 1] = __float2half_rn(v1);
    });
    __syncthreads();
    store_tile_coalesced(sh, g_v_hi + (size_t)b * Nn * Nn, m0, n0, Nn);
}

// counter = softplus(v @ W_exp[1:] + csum*W_exp[0] + b_exp); staged epilogue
__global__ __launch_bounds__(256, 2) void k_mma_counter(const float* __restrict__ W_exp,
                                                        const float* __restrict__ b_exp) {
    const int b = blockIdx.z, m0 = blockIdx.y * 128, n0 = blockIdx.x * 128;
    float c[2][8][4] = {};
    mma_gemm(Nn / 32,
        [&](int kc, const f16** P, int* ld) {
            size_t a = ((size_t)b * Nn + m0) * Nn + kc * 32;
            size_t o = (size_t)n0 * Dd + kc * 32;
            P[0] = g_v_hi + a; P[1] = g_weT_hi + o;
            ld[0] = Nn; ld[1] = Dd;
        }, c);
    extern __shared__ char smem[];
    f16* sh = (f16*)smem;   // [128][EPAD]
    epi_loop(0, 0, c, [&](int r, int lcol, float v0, float v1) {
        const float cs = g_csum[b * Nn + m0 + r];
        const int col = n0 + lcol;
        float x0 = v0 + cs * W_exp[col] + b_exp[col];
        float x1 = v1 + cs * W_exp[col + 1] + b_exp[col + 1];
        float s0 = fmaxf(x0, 0.f) + log1pf(__expf(-fabsf(x0)));
        float s1 = fmaxf(x1, 0.f) + log1pf(__expf(-fabsf(x1)));
        sh[r * EPAD + lcol]     = __float2half_rn(s0);
        sh[r * EPAD + lcol + 1] = __float2half_rn(s1);
    });
    __syncthreads();
    store_tile_coalesced(sh, g_ctr_hi + (size_t)b * Nn * Dd, m0, n0, Dd);
}

// out = data @ W_merge[:D] + counter @ W_merge[D:], 1-pass, fp32 out
// (float2 stores already fill 32B sectors; no staging needed)
__global__ __launch_bounds__(256, 2) void k_mma_out(float* __restrict__ outp) {
    const int b = blockIdx.z, m0 = blockIdx.y * 128, n0 = blockIdx.x * 128;
    float c[2][8][4] = {};
    mma_gemm(2 * Dd / 32,
        [&](int kc, const f16** P, int* ld) {
            if (kc < Dd / 32) {
                size_t a = ((size_t)b * Nn + m0) * Dd + kc * 32;
                size_t o = (size_t)n0 * (2 * Dd) + kc * 32;
                P[0] = g_dat_hi + a; P[1] = g_wmT_hi + o;
            } else {
                size_t a = ((size_t)b * Nn + m0) * Dd + (kc - Dd / 32) * 32;
                size_t o = (size_t)n0 * (2 * Dd) + Dd + (kc - Dd / 32) * 32;
                P[0] = g_ctr_hi + a; P[1] = g_wmT_hi + o;
            }
            ld[0] = Dd; ld[1] = 2 * Dd;
        }, c);
    epi_loop(m0, n0, c, [&](int row, int col, float v0, float v1) {
        size_t o = ((size_t)b * Nn + row) * Dd + col;
        float2 v; v.x = v0; v.y = v1;
        *(float2*)(outp + o) = v;
    });
}

// =================== prep / pointwise kernels ===================

__global__ __launch_bounds__(256) void k_prep_data(const float* __restrict__ data) {
    const int row = blockIdx.x;  // b*Nn + n
    if (threadIdx.x == 0) g_csum[row] = 0.f;   // zero for fused rowsum atomics
    const float4* in4 = (const float4*)(data + (size_t)row * Dd);
    float s = 0.f;
    float4 v[2];
    #pragma unroll
    for (int it = 0; it < 2; ++it) {
        v[it] = in4[threadIdx.x + it * 256];
        s += v[it].x * v[it].x + v[it].y * v[it].y + v[it].z * v[it].z + v[it].w * v[it].w;
    }
    __shared__ float red[32];
    #pragma unroll
    for (int o = 16; o; o >>= 1) s += __shfl_down_sync(0xffffffffu, s, o);
    if ((threadIdx.x & 31) == 0) red[threadIdx.x >> 5] = s;
    __syncthreads();
    if (threadIdx.x < 32) {
        float q = (threadIdx.x < 8) ? red[threadIdx.x] : 0.f;
        #pragma unroll
        for (int o = 4; o; o >>= 1) q += __shfl_down_sync(0xffffffffu, q, o);
        if (threadIdx.x == 0) red[0] = rsqrtf(fmaxf(q, 1e-12f));
    }
    __syncthreads();
    const float r = red[0];
    size_t base4 = (size_t)row * (Dd / 4);   // in units of 4 halves (8B)
    uint2* dat2 = (uint2*)g_dat_hi;
    uint2* cn2  = (uint2*)g_cn_hi;
    #pragma unroll
    for (int it = 0; it < 2; ++it) {
        const int i = threadIdx.x + it * 256;
        __half2 d0 = __floats2half2_rn(v[it].x, v[it].y);
        __half2 d1 = __floats2half2_rn(v[it].z, v[it].w);
        uint2 pd; pd.x = *(uint32_t*)&d0; pd.y = *(uint32_t*)&d1;
        dat2[base4 + i] = pd;
        __half2 c0 = __floats2half2_rn(v[it].x * r, v[it].y * r);
        __half2 c1 = __floats2half2_rn(v[it].z * r, v[it].w * r);
        uint2 pc; pc.x = *(uint32_t*)&c0; pc.y = *(uint32_t*)&c1;
        cn2[base4 + i] = pc;
    }
}

// one thread per (sin,cos) pair: pe[n][2j] = sin(ang), pe[n][2j+1] = cos(ang)
__global__ __launch_bounds__(256) void k_prep_pe() {
    const int p = blockIdx.x * 256 + threadIdx.x;   // over Nn * (Dd/2)
    const int n = p >> 10;                          // Dd/2 = 1024
    const int j = p & 1023;
    const float e = (float)(2 * j) / (float)Dd;
    const float rate = exp2f(-13.28771238f * e);    // 1/10000^e
    const float ang = (float)n * rate;
    float sn, cs;
    sincosf(ang, &sn, &cs);
    __half2 h = __floats2half2_rn(sn, cs);
    *(__half2*)(g_pe_hi + (size_t)n * Dd + 2 * j) = h;
}

// W_expT[n][k] = W_exp[(k+1)*Dd + n]. Tile 64k x 32n; half2 writes (128B/warp).
__global__ void k_prep_weT(const float* __restrict__ W_exp) {
    __shared__ float t[32][65];   // [n][k]
    const int n0 = blockIdx.x * 32;
    const int k0 = blockIdx.y * 64;
    #pragma unroll
    for (int i = 0; i < 2; ++i) {
        int k = 2 * threadIdx.y + i;
        t[threadIdx.x][k] = W_exp[(size_t)(k0 + k + 1) * Dd + n0 + threadIdx.x];
    }
    __syncthreads();
    const int n = threadIdx.y;
    const int kk = 2 * threadIdx.x;
    __half2 h = __floats2half2_rn(t[n][kk], t[n][kk + 1]);
    *(__half2*)(g_weT_hi + (size_t)(n0 + n) * Dd + k0 + kk) = h;
}

// W_mergeT[n][k] = W_merge[k*Dd + n], k in [0,4096). Tile 64k x 32n.
__global__ void k_prep_wmT(const float* __restrict__ W_merge) {
    __shared__ float t[32][65];   // [n][k]
    const int n0 = blockIdx.x * 32;
    const int k0 = blockIdx.y * 64;
    #pragma unroll
    for (int i = 0; i < 2; ++i) {
        int k = 2 * threadIdx.y + i;
        t[threadIdx.x][k] = W_merge[(size_t)(k0 + k) * Dd + n0 + threadIdx.x];
    }
    __syncthreads();
    const int n = threadIdx.y;
    const int kk = 2 * threadIdx.x;
    __half2 h = __floats2half2_rn(t[n][kk], t[n][kk + 1]);
    *(__half2*)(g_wmT_hi + (size_t)(n0 + n) * (2 * Dd) + k0 + kk) = h;
}

// =================== launch ===================

extern "C" void kernel_launch(void* const* d_in, const int* in_sizes, int n_in,
                              void* d_out, int out_size) {
    const float* data    = (const float*)d_in[0];
    const float* W_exp   = (const float*)d_in[1];
    const float* b_exp   = (const float*)d_in[2];
    const float* W_merge = (const float*)d_in[3];
    float* out = (float*)d_out;
    (void)in_sizes; (void)n_in; (void)out_size;

    // one-time side stream + events (created on the uncaptured correctness
    // call; reused identically on the captured call — deterministic DAG)
    static cudaStream_t s2 = nullptr;
    static cudaEvent_t evRoot = nullptr, evSide = nullptr;
    if (s2 == nullptr) {
        cudaStreamCreateWithFlags(&s2, cudaStreamNonBlocking);
        cudaEventCreateWithFlags(&evRoot, cudaEventDisableTiming);
        cudaEventCreateWithFlags(&evSide, cudaEventDisableTiming);
        cudaFuncSetAttribute(k_mma_sim,     cudaFuncAttributeMaxDynamicSharedMemorySize, SMEM_GE);
        cudaFuncSetAttribute(k_mma_v,       cudaFuncAttributeMaxDynamicSharedMemorySize, SMEM_GE);
        cudaFuncSetAttribute(k_mma_counter, cudaFuncAttributeMaxDynamicSharedMemorySize, SMEM_GE);
        cudaFuncSetAttribute(k_mma_out,     cudaFuncAttributeMaxDynamicSharedMemorySize, SMEM_GE);
    }

    const dim3 tgrid(Nn / 128, Nn / 128, Bb);

    // fork: pe/weT/wmT are independent of data-prep and sim
    cudaEventRecord(evRoot, 0);
    cudaStreamWaitEvent(s2, evRoot, 0);
    k_prep_pe<<<(Nn * (Dd / 2)) / 256, 256, 0, s2>>>();
    k_prep_weT<<<dim3(Dd / 32, Dd / 64), dim3(32, 32), 0, s2>>>(W_exp);
    k_prep_wmT<<<dim3(Dd / 32, (2 * Dd) / 64), dim3(32, 32), 0, s2>>>(W_merge);
    cudaEventRecord(evSide, s2);

    // main chain
    k_prep_data<<<Bb * Nn, 256>>>(data);
    k_mma_sim<<<dim3(136, 1, Bb), 256, SMEM_GE>>>();

    // join before consumers of pe/weT/wmT
    cudaStreamWaitEvent(0, evSide, 0);
    k_mma_v<<<tgrid, 256, SMEM_GE>>>();
    k_mma_counter<<<tgrid, 256, SMEM_GE>>>(W_exp, b_exp);
    k_mma_out<<<tgrid, 256, SMEM_GE>>>(out);
}